// round 9
// baseline (speedup 1.0000x reference)
#include <cuda_runtime.h>
#include <cuda_bf16.h>
#include <cstdint>

// Problem constants (fixed shapes)
#define D_MODEL 1024
#define RANK    256
#define R2      (2*RANK)          // 512
#define NPROJ   (R2 + R2 + RANK)  // 1280 = [a_b|a_t | c_b|c_t | z]
#define BATCH   4
#define SEQ     2048
#define MTOT    (BATCH*SEQ)       // 8192
#define TCH     128
#define NCH     (SEQ/TCH)         // 16
#define SCANC   (R2 + RANK)       // 768
#define PSLICE  (1024*1024 + 1024*512)   // 1.5M floats per k-slice partial
#define NBROWS  (NPROJ + 1024)    // combine_quant rows: 1280 Bp + 1024 UWo

// ---------------- scratch (device globals; no cudaMalloc allowed) ------------
__device__ float         g_H   [MTOT*NPROJ];   // reused as prep partial scratch first
__device__ float         g_XtT [RANK*D_MODEL];
__device__ int8_t        g_xq1 [MTOT*D_MODEL], g_xq2[MTOT*D_MODEL];
__device__ float         g_sx  [MTOT];
__device__ int8_t        g_Bq1 [NPROJ*D_MODEL], g_Bq2[NPROJ*D_MODEL];
__device__ float         g_sB  [NPROJ];
__device__ int8_t        g_Gq1 [MTOT*R2], g_Gq2[MTOT*R2];
__device__ float         g_sG  [MTOT];
__device__ int8_t        g_Uq1 [D_MODEL*R2], g_Uq2[D_MODEL*R2];
__device__ float         g_sU  [D_MODEL];
__device__ __nv_bfloat16 g_WqTh[D_MODEL*D_MODEL], g_WqTl[D_MODEL*D_MODEL];
__device__ __nv_bfloat16 g_WkTh[D_MODEL*D_MODEL], g_WkTl[D_MODEL*D_MODEL];
__device__ __nv_bfloat16 g_VcTh[R2*D_MODEL],      g_VcTl[R2*D_MODEL];
__device__ __nv_bfloat16 g_WcTh[R2*D_MODEL],      g_WcTl[R2*D_MODEL];
__device__ __nv_bfloat16 g_UcTh[R2*D_MODEL],      g_UcTl[R2*D_MODEL];
__device__ __nv_bfloat16 g_Woh [D_MODEL*D_MODEL], g_Wol [D_MODEL*D_MODEL];
__device__ float g_bo [D_MODEL];
__device__ float g_cs [BATCH*NCH*SCANC];

// ====================== helpers ==============================================
#define LDSM_X4(R, A) \
    asm volatile("ldmatrix.sync.aligned.m8n8.x4.shared.b16 {%0,%1,%2,%3}, [%4];" \
        : "=r"((R)[0]), "=r"((R)[1]), "=r"((R)[2]), "=r"((R)[3]) : "r"(A))
#define MMA_BF16(D, Ar, Br) \
    asm volatile("mma.sync.aligned.m16n8k16.row.col.f32.bf16.bf16.f32 " \
        "{%0,%1,%2,%3}, {%4,%5,%6,%7}, {%8,%9}, {%0,%1,%2,%3};" \
        : "+f"((D)[0]), "+f"((D)[1]), "+f"((D)[2]), "+f"((D)[3]) \
        : "r"((Ar)[0]), "r"((Ar)[1]), "r"((Ar)[2]), "r"((Ar)[3]), \
          "r"((Br)[0]), "r"((Br)[1]))
#define MMA_S8(D, Ar, Br) \
    asm volatile("mma.sync.aligned.m16n8k32.row.col.s32.s8.s8.s32 " \
        "{%0,%1,%2,%3}, {%4,%5,%6,%7}, {%8,%9}, {%0,%1,%2,%3};" \
        : "+r"((D)[0]), "+r"((D)[1]), "+r"((D)[2]), "+r"((D)[3]) \
        : "r"((Ar)[0]), "r"((Ar)[1]), "r"((Ar)[2]), "r"((Ar)[3]), \
          "r"((Br)[0]), "r"((Br)[1]))

__device__ __forceinline__ uint32_t smem_u32(const void* p) {
    uint32_t a;
    asm("{ .reg .u64 t; cvta.to.shared.u64 t, %1; cvt.u32.u64 %0, t; }" : "=r"(a) : "l"(p));
    return a;
}

// bf16 path swizzle: rows of 64B paired into 128B physical rows
__device__ __forceinline__ uint32_t swoff(int m, int c) {
    const int p  = m >> 1;
    const int cc = (((m & 1) << 2) | c) ^ (p & 7);
    return (uint32_t)(p * 128 + cc * 16);
}
// int8 path swizzle: rows of 32B, 4 per 128B physical row; c in {0,1}
__device__ __forceinline__ uint32_t swoff8(int m, int c) {
    const int p  = m >> 2;
    const int cc = (((m & 3) << 1) | c) ^ (p & 7);
    return (uint32_t)(p * 128 + cc * 16);
}

__device__ __forceinline__ uint32_t pack2(__nv_bfloat16 x, __nv_bfloat16 y) {
    return (uint32_t)__bfloat16_as_ushort(x) | ((uint32_t)__bfloat16_as_ushort(y) << 16);
}
__device__ __forceinline__ void bf_split(float v, __nv_bfloat16& h, __nv_bfloat16& l) {
    h = __float2bfloat16(v);
    l = __float2bfloat16(v - __bfloat162float(h));
}
__device__ __forceinline__ void quant2(float v, float inv, int& q1, int& q2) {
    const float q = v * inv;
    q1 = __float2int_rn(q);
    int i2 = __float2int_rn((q - (float)q1) * 256.f);
    q2 = max(-127, min(127, i2));
}

__device__ __forceinline__ void cpasync16(uint32_t dst, const void* src) {
    asm volatile("cp.async.cg.shared.global [%0], [%1], 16;" :: "r"(dst), "l"(src));
}
#define CP_COMMIT() asm volatile("cp.async.commit_group;" ::: "memory")
#define CP_WAIT1()  asm volatile("cp.async.wait_group 1;"  ::: "memory")
#define CP_WAIT2()  asm volatile("cp.async.wait_group 2;"  ::: "memory")

// ====================== bf16 GEMM core (prep path, as R8) ====================
#define TILE_B     8192
#define STAGE_B    32768
#define PRE_SMEM   (3*STAGE_B)   // 96 KB

__device__ __forceinline__ void gemm_core(
    const __nv_bfloat16* __restrict__ Ah_g, const __nv_bfloat16* __restrict__ Al_g,
    const __nv_bfloat16* __restrict__ Bh_g, const __nv_bfloat16* __restrict__ Bl_g,
    int K, int kbeg, int kend, long bm, long bn, uint32_t sb, float acc[4][4][4])
{
    const int tid  = threadIdx.x;
    const int wid  = tid >> 5, lane = tid & 31;
    const int warpM = wid & 1, warpN = wid >> 1;

    uint32_t offA0[2], offBx[2];
#pragma unroll
    for (int kg = 0; kg < 2; kg++) {
        offA0[kg] = swoff(warpM * 64 + (lane & 15), 2 * kg + (lane >> 4));
        offBx[kg] = swoff(warpN * 32 + ((lane >> 4) << 3) + (lane & 7),
                          2 * kg + ((lane >> 3) & 1));
    }

    const int mrow = tid >> 2, mc = tid & 3;
    const uint32_t so0 = swoff(mrow, mc), so1 = swoff(mrow + 64, mc);

    auto issue = [&](int kt) {
        const uint32_t base = sb + (uint32_t)(kt % 3) * STAGE_B;
        const long koff = (long)kt * 32 + mc * 8;
        const long gA0 = (bm + mrow) * (long)K + koff;
        const long gA1 = gA0 + 64L * K;
        const long gB0 = (bn + mrow) * (long)K + koff;
        const long gB1 = gB0 + 64L * K;
        cpasync16(base + so0,            Ah_g + gA0);
        cpasync16(base + so1,            Ah_g + gA1);
        cpasync16(base + TILE_B + so0,   Al_g + gA0);
        cpasync16(base + TILE_B + so1,   Al_g + gA1);
        cpasync16(base + 2*TILE_B + so0, Bh_g + gB0);
        cpasync16(base + 2*TILE_B + so1, Bh_g + gB1);
        cpasync16(base + 3*TILE_B + so0, Bl_g + gB0);
        cpasync16(base + 3*TILE_B + so1, Bl_g + gB1);
    };

    issue(kbeg);     CP_COMMIT();
    issue(kbeg + 1); CP_COMMIT();

#pragma unroll 1
    for (int kt = kbeg; kt < kend; kt++) {
        CP_WAIT1();
        __syncthreads();
        if (kt + 2 < kend) issue(kt + 2);
        CP_COMMIT();

        const uint32_t bb = sb + (uint32_t)(kt % 3) * STAGE_B;
#pragma unroll
        for (int kg = 0; kg < 2; kg++) {
            uint32_t bh[4][2], bl[4][2];
#pragma unroll
            for (int jp = 0; jp < 2; jp++) {
                uint32_t rh[4], rl[4];
                LDSM_X4(rh, bb + 2*TILE_B + offBx[kg] + (uint32_t)jp * 1024);
                LDSM_X4(rl, bb + 3*TILE_B + offBx[kg] + (uint32_t)jp * 1024);
                bh[2*jp][0]   = rh[0]; bh[2*jp][1]   = rh[1];
                bh[2*jp+1][0] = rh[2]; bh[2*jp+1][1] = rh[3];
                bl[2*jp][0]   = rl[0]; bl[2*jp][1]   = rl[1];
                bl[2*jp+1][0] = rl[2]; bl[2*jp+1][1] = rl[3];
            }
#pragma unroll
            for (int i = 0; i < 4; i++) {
                uint32_t ah[4], al[4];
                const uint32_t ao = bb + offA0[kg] + (uint32_t)i * 1024;
                LDSM_X4(ah, ao);
                LDSM_X4(al, ao + TILE_B);
#pragma unroll
                for (int j = 0; j < 4; j++) {
                    MMA_BF16(acc[i][j], ah, bh[j]);
                    MMA_BF16(acc[i][j], ah, bl[j]);
                    MMA_BF16(acc[i][j], al, bh[j]);
                }
            }
        }
    }
}

// ---------------- prep GEMM: compact tiles, split-K x3, fp32 partials --------
__global__ __launch_bounds__(256, 2)
void gemm_prep(const __nv_bfloat16* __restrict__ VcTh, const __nv_bfloat16* __restrict__ VcTl,
               const __nv_bfloat16* __restrict__ WqTh, const __nv_bfloat16* __restrict__ WqTl,
               const __nv_bfloat16* __restrict__ WcTh, const __nv_bfloat16* __restrict__ WcTl,
               const __nv_bfloat16* __restrict__ WkTh, const __nv_bfloat16* __restrict__ WkTl,
               const __nv_bfloat16* __restrict__ Woh,  const __nv_bfloat16* __restrict__ Wol,
               const __nv_bfloat16* __restrict__ UcTh, const __nv_bfloat16* __restrict__ UcTl,
               float* __restrict__ P)
{
    const int t = blockIdx.x, s = blockIdx.y;
    const __nv_bfloat16 *Ah, *Al, *Bh, *Bl;
    long bm, bn, ooff; int ldc;
    if (t < 32)      { Ah=VcTh; Al=VcTl; Bh=WqTh; Bl=WqTl; bm=(t>>3)*128;      bn=(t&7)*128;      ldc=1024; ooff=0; }
    else if (t < 64) { Ah=WcTh; Al=WcTl; Bh=WkTh; Bl=WkTl; bm=((t-32)>>3)*128; bn=((t-32)&7)*128; ldc=1024; ooff=512L*1024; }
    else             { Ah=Woh;  Al=Wol;  Bh=UcTh; Bl=UcTl; bm=((t-64)>>2)*128; bn=((t-64)&3)*128; ldc=512;  ooff=1024L*1024; }
    const int K = 1024;
    const int kbeg = s * 11, kend = (s == 2) ? 32 : kbeg + 11;
    float* Cp = P + (long)s * PSLICE + ooff;

    extern __shared__ __align__(128) char sm[];
    const uint32_t sb = smem_u32(sm);

    float acc[4][4][4];
#pragma unroll
    for (int i = 0; i < 4; i++)
#pragma unroll
        for (int j = 0; j < 4; j++)
#pragma unroll
            for (int q = 0; q < 4; q++) acc[i][j][q] = 0.f;

    gemm_core(Ah, Al, Bh, Bl, K, kbeg, kend, bm, bn, sb, acc);

    const int tid = threadIdx.x, wid = tid >> 5, lane = tid & 31;
    const int warpM = wid & 1, warpN = wid >> 1;
    const int g = lane >> 2, tg = lane & 3;
#pragma unroll
    for (int i = 0; i < 4; i++) {
        const long row = bm + warpM * 64 + i * 16 + g;
#pragma unroll
        for (int j = 0; j < 4; j++) {
            const int col = (int)bn + warpN * 32 + j * 8 + 2 * tg;
            *(float2*)(Cp + row * ldc + col)       = make_float2(acc[i][j][0], acc[i][j][1]);
            *(float2*)(Cp + (row + 8) * ldc + col) = make_float2(acc[i][j][2], acc[i][j][3]);
        }
    }
}

// ====================== int8 2-digit GEMM (main path) ========================
// C = sa[row]*sb[col]*( (q1a q1b) + (q1a q2b + q2a q1b)/256 ), K bytes per row.
// 128x128 CTA, 512 threads (16 warps, warp tile 32x32), BK=32, 4 stages x 16KB.
#define I8_PLANE  4096
#define I8_STAGE  16384
#define I8_SMEM   (4*I8_STAGE)   // 64 KB

template<bool BIAS>
__global__ __launch_bounds__(512, 1)
void gemm_i8(const int8_t* __restrict__ Aq1, const int8_t* __restrict__ Aq2,
             const float* __restrict__ sa,
             const int8_t* __restrict__ Bq1, const int8_t* __restrict__ Bq2,
             const float* __restrict__ sbv,
             float* __restrict__ C, int N, int K, const float* __restrict__ bias)
{
    extern __shared__ __align__(128) char sm[];
    const uint32_t sb = smem_u32(sm);
    const int tid = threadIdx.x, wid = tid >> 5, lane = tid & 31;
    const long bm = (long)blockIdx.y * 128, bn = (long)blockIdx.x * 128;
    const int m0 = (wid & 3) * 32, n0 = (wid >> 2) * 32;

    // ldmatrix source offsets
    uint32_t offA[2], offB[2];
#pragma unroll
    for (int i = 0; i < 2; i++)
        offA[i] = swoff8(m0 + i * 16 + (lane & 15), lane >> 4);
#pragma unroll
    for (int jp = 0; jp < 2; jp++)
        offB[jp] = swoff8(n0 + jp * 16 + (lane & 7) + ((lane >> 4) << 3), (lane >> 3) & 1);

    // cp.async mapping: 1024 16B-chunks per stage, 2 per thread
    auto issue = [&](int kt) {
        const uint32_t base = sb + (uint32_t)(kt & 3) * I8_STAGE;
#pragma unroll
        for (int rep = 0; rep < 2; rep++) {
            const int id = tid + 512 * rep;
            const int plane = id >> 8, cid = id & 255;
            const int m = cid >> 1, c = cid & 1;
            const uint32_t dst = base + (uint32_t)plane * I8_PLANE + swoff8(m, c);
            const long ko = (long)kt * 32 + c * 16;
            const int8_t* src;
            if      (plane == 0) src = Aq1 + (bm + m) * (long)K + ko;
            else if (plane == 1) src = Aq2 + (bm + m) * (long)K + ko;
            else if (plane == 2) src = Bq1 + (bn + m) * (long)K + ko;
            else                 src = Bq2 + (bn + m) * (long)K + ko;
            cpasync16(dst, src);
        }
    };

    int hi[2][4][4], xx[2][4][4];
#pragma unroll
    for (int i = 0; i < 2; i++)
#pragma unroll
        for (int j = 0; j < 4; j++)
#pragma unroll
            for (int q = 0; q < 4; q++) { hi[i][j][q] = 0; xx[i][j][q] = 0; }

    const int nk = K / 32;
    issue(0); CP_COMMIT();
    issue(1); CP_COMMIT();
    issue(2); CP_COMMIT();

#pragma unroll 1
    for (int kt = 0; kt < nk; kt++) {
        CP_WAIT2();
        __syncthreads();
        if (kt + 3 < nk) issue(kt + 3);
        CP_COMMIT();

        const uint32_t bb = sb + (uint32_t)(kt & 3) * I8_STAGE;
        uint32_t b1[4][2], b2[4][2];
#pragma unroll
        for (int jp = 0; jp < 2; jp++) {
            uint32_t r1[4], r2[4];
            LDSM_X4(r1, bb + 2*I8_PLANE + offB[jp]);
            LDSM_X4(r2, bb + 3*I8_PLANE + offB[jp]);
            b1[2*jp][0]   = r1[0]; b1[2*jp][1]   = r1[1];
            b1[2*jp+1][0] = r1[2]; b1[2*jp+1][1] = r1[3];
            b2[2*jp][0]   = r2[0]; b2[2*jp][1]   = r2[1];
            b2[2*jp+1][0] = r2[2]; b2[2*jp+1][1] = r2[3];
        }
#pragma unroll
        for (int i = 0; i < 2; i++) {
            uint32_t a1[4], a2[4];
            LDSM_X4(a1, bb + offA[i]);
            LDSM_X4(a2, bb + I8_PLANE + offA[i]);
#pragma unroll
            for (int j = 0; j < 4; j++) {
                MMA_S8(hi[i][j], a1, b1[j]);
                MMA_S8(xx[i][j], a1, b2[j]);
                MMA_S8(xx[i][j], a2, b1[j]);
            }
        }
    }

    const int g = lane >> 2, tg = lane & 3;
#pragma unroll
    for (int i = 0; i < 2; i++) {
        const long row = bm + m0 + i * 16 + g;
        const float sA0 = sa[row], sA1 = sa[row + 8];
#pragma unroll
        for (int j = 0; j < 4; j++) {
            const int col = (int)bn + n0 + j * 8 + 2 * tg;
            const float s0 = sbv[col], s1 = sbv[col + 1];
            float b0 = 0.f, b1_ = 0.f;
            if (BIAS) { b0 = bias[col]; b1_ = bias[col + 1]; }
            const float k = 1.f / 256.f;
            float2 v0, v1;
            v0.x = sA0 * s0 * ((float)hi[i][j][0] + (float)xx[i][j][0] * k) + b0;
            v0.y = sA0 * s1 * ((float)hi[i][j][1] + (float)xx[i][j][1] * k) + b1_;
            v1.x = sA1 * s0 * ((float)hi[i][j][2] + (float)xx[i][j][2] * k) + b0;
            v1.y = sA1 * s1 * ((float)hi[i][j][3] + (float)xx[i][j][3] * k) + b1_;
            *(float2*)(C + row * N + col)       = v0;
            *(float2*)(C + (row + 8) * N + col) = v1;
        }
    }
}

// ====================== batched transpose / split (weights) ==================
// z=0: Wq->WqT(h/l); z=1: Wk->WkT(h/l); z=2..7: V/W/U concatT (h/l);
// z=8: X_t -> fp32 XtT; z=9: Wo -> straight split Woh/Wol
__global__ void trans_batched(const float* __restrict__ Wq, const float* __restrict__ Wk,
                              const float* __restrict__ V_b, const float* __restrict__ V_t,
                              const float* __restrict__ W_b, const float* __restrict__ W_t,
                              const float* __restrict__ U_b, const float* __restrict__ U_t,
                              const float* __restrict__ X_t, const float* __restrict__ Wo,
                              __nv_bfloat16* __restrict__ WqTh, __nv_bfloat16* __restrict__ WqTl,
                              __nv_bfloat16* __restrict__ WkTh, __nv_bfloat16* __restrict__ WkTl,
                              __nv_bfloat16* __restrict__ VcTh, __nv_bfloat16* __restrict__ VcTl,
                              __nv_bfloat16* __restrict__ WcTh, __nv_bfloat16* __restrict__ WcTl,
                              __nv_bfloat16* __restrict__ UcTh, __nv_bfloat16* __restrict__ UcTl,
                              float* __restrict__ XtT,
                              __nv_bfloat16* __restrict__ Woh,  __nv_bfloat16* __restrict__ Wol)
{
    __shared__ float t[32][33];
    const int z = blockIdx.z;
    const int bx = blockIdx.x, by = blockIdx.y;
    const int tx = threadIdx.x, ty = threadIdx.y;

    if (z == 9) {
#pragma unroll
        for (int j = 0; j < 32; j += 8) {
            const long o = (long)(by * 32 + ty + j) * 1024 + bx * 32 + tx;
            __nv_bfloat16 h, l;
            bf_split(Wo[o], h, l);
            Woh[o] = h; Wol[o] = l;
        }
        return;
    }

    const float* src; int Cin;
    __nv_bfloat16 *Dh = nullptr, *Dl = nullptr; int roff = 0; bool f32out = false;
    switch (z) {
        case 0: src = Wq;  Cin = 1024; Dh = WqTh; Dl = WqTl; break;
        case 1: src = Wk;  Cin = 1024; Dh = WkTh; Dl = WkTl; break;
        case 2: src = V_b; Cin = 256;  Dh = VcTh; Dl = VcTl; roff = 0;    break;
        case 3: src = V_t; Cin = 256;  Dh = VcTh; Dl = VcTl; roff = 256;  break;
        case 4: src = W_b; Cin = 256;  Dh = WcTh; Dl = WcTl; roff = 0;    break;
        case 5: src = W_t; Cin = 256;  Dh = WcTh; Dl = WcTl; roff = 256;  break;
        case 6: src = U_b; Cin = 256;  Dh = UcTh; Dl = UcTl; roff = 0;    break;
        case 7: src = U_t; Cin = 256;  Dh = UcTh; Dl = UcTl; roff = 256;  break;
        default: src = X_t; Cin = 256; f32out = true; break;
    }
    if (Cin == 256 && bx >= 8) return;
#pragma unroll
    for (int j = 0; j < 32; j += 8)
        t[ty + j][tx] = src[(long)(by * 32 + ty + j) * Cin + bx * 32 + tx];
    __syncthreads();
    if (f32out) {
#pragma unroll
        for (int j = 0; j < 32; j += 8)
            XtT[(long)(bx * 32 + ty + j) * 1024 + by * 32 + tx] = t[tx][ty + j];
    } else {
#pragma unroll
        for (int j = 0; j < 32; j += 8) {
            __nv_bfloat16 h, l;
            bf_split(t[tx][ty + j], h, l);
            const long o = (long)(roff + bx * 32 + ty + j) * 1024 + by * 32 + tx;
            Dh[o] = h; Dl[o] = l;
        }
    }
}

// ---------------- quantize x: row-wise 2-digit int8 --------------------------
__global__ __launch_bounds__(256)
void quant_x(const float* __restrict__ x, int8_t* __restrict__ q1,
             int8_t* __restrict__ q2, float* __restrict__ sx)
{
    __shared__ float red[256];
    const int m = blockIdx.x, t = threadIdx.x;
    const float4 v = ((const float4*)(x + (long)m * D_MODEL))[t];
    float mx = fmaxf(fmaxf(fabsf(v.x), fabsf(v.y)), fmaxf(fabsf(v.z), fabsf(v.w)));
    red[t] = mx;
    __syncthreads();
    for (int s = 128; s > 0; s >>= 1) {
        if (t < s) red[t] = fmaxf(red[t], red[t + s]);
        __syncthreads();
    }
    const float rmax = red[0];
    const float inv = rmax > 0.f ? 127.f / rmax : 0.f;
    if (t == 0) sx[m] = rmax / 127.f;
    int a1, a2, b1, b2, c1, c2, d1, d2;
    quant2(v.x, inv, a1, a2); quant2(v.y, inv, b1, b2);
    quant2(v.z, inv, c1, c2); quant2(v.w, inv, d1, d2);
    const uint32_t p1 = (a1 & 0xFF) | ((b1 & 0xFF) << 8) | ((c1 & 0xFF) << 16) | ((d1 & 0xFF) << 24);
    const uint32_t p2 = (a2 & 0xFF) | ((b2 & 0xFF) << 8) | ((c2 & 0xFF) << 16) | ((d2 & 0xFF) << 24);
    ((uint32_t*)(q1 + (long)m * D_MODEL))[t] = p1;
    ((uint32_t*)(q2 + (long)m * D_MODEL))[t] = p2;
}

// ---------------- combine prep partials + quantize (Bp rows + UWo rows) ------
__global__ __launch_bounds__(256)
void combine_quant(const float* __restrict__ P, const float* __restrict__ XtT,
                   int8_t* __restrict__ Bq1, int8_t* __restrict__ Bq2, float* __restrict__ sB,
                   int8_t* __restrict__ Uq1, int8_t* __restrict__ Uq2, float* __restrict__ sU)
{
    __shared__ float red[256];
    const int b = blockIdx.x, t = threadIdx.x;
    float v[4];
    int C; long base; int nv;
    int8_t *o1, *o2; float* sout; long obase;
    if (b < 1024) {           // Bp rows 0..1023 (composed)
        C = 1024; nv = 4; base = (long)b * 1024;
#pragma unroll
        for (int k = 0; k < 4; k++) {
            const long i = base + t + 256 * k;
            v[k] = P[i] + P[PSLICE + i] + P[2L * PSLICE + i];
        }
        o1 = Bq1; o2 = Bq2; sout = sB + b; obase = base;
    } else if (b < NPROJ) {   // Bp rows 1024..1279 (= XtT direct)
        C = 1024; nv = 4; base = (long)(b - 1024) * 1024;
#pragma unroll
        for (int k = 0; k < 4; k++) v[k] = XtT[base + t + 256 * k];
        o1 = Bq1; o2 = Bq2; sout = sB + b; obase = (long)b * 1024;
    } else {                  // UWo rows
        const int r = b - NPROJ;
        C = 512; nv = 2; base = 1024L * 1024 + (long)r * 512;
#pragma unroll
        for (int k = 0; k < 2; k++) {
            const long i = base + t + 256 * k;
            v[k] = P[i] + P[PSLICE + i] + P[2L * PSLICE + i];
        }
        v[2] = v[3] = 0.f;
        o1 = Uq1; o2 = Uq2; sout = sU + r; obase = (long)r * 512;
    }
    float mx = 0.f;
#pragma unroll
    for (int k = 0; k < 4; k++) mx = fmaxf(mx, fabsf(v[k]));
    red[t] = mx;
    __syncthreads();
    for (int s = 128; s > 0; s >>= 1) {
        if (t < s) red[t] = fmaxf(red[t], red[t + s]);
        __syncthreads();
    }
    const float rmax = red[0];
    const float inv = rmax > 0.f ? 127.f / rmax : 0.f;
    if (t == 0) *sout = rmax / 127.f;
    for (int k = 0; k < nv; k++) {
        int i1, i2;
        quant2(v[k], inv, i1, i2);
        o1[obase + t + 256 * k] = (int8_t)i1;
        o2[obase + t + 256 * k] = (int8_t)i2;
    }
    (void)C;
}

// ---------------- causal cumulative scan (cols 512..1280 of H) ---------------
__global__ void scan_partial(float* __restrict__ Hc, float* __restrict__ cs)
{
    const int col = blockIdx.x * 128 + threadIdx.x;
    const int ch  = blockIdx.y;
    const int b   = blockIdx.z;
    const long base = ((long)b * SEQ + (long)ch * TCH) * NPROJ + col;
    float run = 0.f;
    for (int t = 0; t < TCH; t++) {
        run += Hc[base + (long)t * NPROJ];
        Hc[base + (long)t * NPROJ] = run;
    }
    cs[((long)b * NCH + ch) * SCANC + col] = run;
}

__global__ void scan_offsets(float* __restrict__ cs)
{
    const int i = blockIdx.x * blockDim.x + threadIdx.x;
    if (i >= BATCH * SCANC) return;
    const int b = i / SCANC, col = i % SCANC;
    float off = 0.f;
    for (int ch = 0; ch < NCH; ch++) {
        const long idx = ((long)b * NCH + ch) * SCANC + col;
        const float v = cs[idx];
        cs[idx] = off;
        off += v;
    }
}

// ---------------- fused scan-apply + G build + row quantize ------------------
__global__ __launch_bounds__(256)
void apply_build_q(const float* __restrict__ H, const float* __restrict__ cs,
                   const float* __restrict__ alpha,
                   int8_t* __restrict__ Gq1, int8_t* __restrict__ Gq2,
                   float* __restrict__ sG)
{
    __shared__ float red[256];
    const int m = blockIdx.x, r = threadIdx.x;   // r in [0,256)
    const int t = m % SEQ, b = m / SEQ, ch = t / TCH;
    const float inv_t = 1.0f / (float)(t + 1);
    const float* hrow = H + (long)m * NPROJ;
    const float* co = cs + ((long)b * NCH + ch) * SCANC;
    const float cb = hrow[512 + r]  + co[r];
    const float ct = hrow[768 + r]  + co[256 + r];
    const float z  = (hrow[1024 + r] + co[512 + r]) * inv_t;
    const float gb = hrow[r] * cb * inv_t;
    const float gt = alpha[0] * hrow[256 + r] * z * ct * inv_t;

    red[r] = fmaxf(fabsf(gb), fabsf(gt));
    __syncthreads();
    for (int s = 128; s > 0; s >>= 1) {
        if (r < s) red[r] = fmaxf(red[r], red[r + s]);
        __syncthreads();
    }
    const float rmax = red[0];
    const float inv = rmax > 0.f ? 127.f / rmax : 0.f;
    if (r == 0) sG[m] = rmax / 127.f;
    int i1, i2;
    const long o = (long)m * R2;
    quant2(gb, inv, i1, i2);
    Gq1[o + r] = (int8_t)i1;        Gq2[o + r] = (int8_t)i2;
    quant2(gt, inv, i1, i2);
    Gq1[o + RANK + r] = (int8_t)i1; Gq2[o + RANK + r] = (int8_t)i2;
}

// bo[d] = sum_e Wo[d,e] * (bias_b[e] + alpha*bias_t[e])
__global__ void bo_kernel(const float* __restrict__ Wo, const float* __restrict__ bb,
                          const float* __restrict__ bt, const float* __restrict__ alpha,
                          float* __restrict__ bo)
{
    const int w = (blockIdx.x * blockDim.x + threadIdx.x) >> 5;
    const int lane = threadIdx.x & 31;
    if (w >= D_MODEL) return;
    const float a = alpha[0];
    float s = 0.f;
    for (int e = lane; e < D_MODEL; e += 32)
        s += Wo[(long)w * D_MODEL + e] * (bb[e] + a * bt[e]);
#pragma unroll
    for (int o = 16; o; o >>= 1) s += __shfl_xor_sync(0xFFFFFFFFu, s, o);
    if (lane == 0) bo[w] = s;
}

// ---------------- launch ------------------------------------------------------
extern "C" void kernel_launch(void* const* d_in, const int* in_sizes, int n_in,
                              void* d_out, int out_size)
{
    const float* x      = (const float*)d_in[0];
    const float* Wq     = (const float*)d_in[1];
    const float* Wk     = (const float*)d_in[2];
    const float* Wo     = (const float*)d_in[3];
    const float* U_b    = (const float*)d_in[4];
    const float* V_b    = (const float*)d_in[5];
    const float* W_b    = (const float*)d_in[6];
    const float* bias_b = (const float*)d_in[7];
    const float* U_t    = (const float*)d_in[8];
    const float* V_t    = (const float*)d_in[9];
    const float* W_t    = (const float*)d_in[10];
    const float* X_t    = (const float*)d_in[11];
    const float* bias_t = (const float*)d_in[12];
    const float* alpha  = (const float*)d_in[13];
    float* out = (float*)d_out;

    float *H, *XtT, *sx, *sB, *sG, *sU, *bo, *cs;
    int8_t *xq1, *xq2, *Bq1, *Bq2, *Gq1, *Gq2, *Uq1, *Uq2;
    __nv_bfloat16 *WqTh, *WqTl, *WkTh, *WkTl, *VcTh, *VcTl, *WcTh, *WcTl, *UcTh, *UcTl, *Woh, *Wol;
    cudaGetSymbolAddress((void**)&H,    g_H);
    cudaGetSymbolAddress((void**)&XtT,  g_XtT);
    cudaGetSymbolAddress((void**)&xq1,  g_xq1);
    cudaGetSymbolAddress((void**)&xq2,  g_xq2);
    cudaGetSymbolAddress((void**)&sx,   g_sx);
    cudaGetSymbolAddress((void**)&Bq1,  g_Bq1);
    cudaGetSymbolAddress((void**)&Bq2,  g_Bq2);
    cudaGetSymbolAddress((void**)&sB,   g_sB);
    cudaGetSymbolAddress((void**)&Gq1,  g_Gq1);
    cudaGetSymbolAddress((void**)&Gq2,  g_Gq2);
    cudaGetSymbolAddress((void**)&sG,   g_sG);
    cudaGetSymbolAddress((void**)&Uq1,  g_Uq1);
    cudaGetSymbolAddress((void**)&Uq2,  g_Uq2);
    cudaGetSymbolAddress((void**)&sU,   g_sU);
    cudaGetSymbolAddress((void**)&WqTh, g_WqTh);
    cudaGetSymbolAddress((void**)&WqTl, g_WqTl);
    cudaGetSymbolAddress((void**)&WkTh, g_WkTh);
    cudaGetSymbolAddress((void**)&WkTl, g_WkTl);
    cudaGetSymbolAddress((void**)&VcTh, g_VcTh);
    cudaGetSymbolAddress((void**)&VcTl, g_VcTl);
    cudaGetSymbolAddress((void**)&WcTh, g_WcTh);
    cudaGetSymbolAddress((void**)&WcTl, g_WcTl);
    cudaGetSymbolAddress((void**)&UcTh, g_UcTh);
    cudaGetSymbolAddress((void**)&UcTl, g_UcTl);
    cudaGetSymbolAddress((void**)&Woh,  g_Woh);
    cudaGetSymbolAddress((void**)&Wol,  g_Wol);
    cudaGetSymbolAddress((void**)&bo,   g_bo);
    cudaGetSymbolAddress((void**)&cs,   g_cs);

    cudaFuncSetAttribute(gemm_prep,      cudaFuncAttributeMaxDynamicSharedMemorySize, PRE_SMEM);
    cudaFuncSetAttribute(gemm_i8<false>, cudaFuncAttributeMaxDynamicSharedMemorySize, I8_SMEM);
    cudaFuncSetAttribute(gemm_i8<true>,  cudaFuncAttributeMaxDynamicSharedMemorySize, I8_SMEM);

    // ---- prep: transposes/splits + bias fold + x quantize ----
    dim3 tgrid(32, 32, 10), tblk(32, 8);
    trans_batched<<<tgrid, tblk>>>(Wq, Wk, V_b, V_t, W_b, W_t, U_b, U_t, X_t, Wo,
                                   WqTh, WqTl, WkTh, WkTl, VcTh, VcTl, WcTh, WcTl,
                                   UcTh, UcTl, XtT, Woh, Wol);
    bo_kernel<<<128, 256>>>(Wo, bias_b, bias_t, alpha, bo);
    quant_x<<<MTOT, 256>>>(x, xq1, xq2, sx);

    // ---- prep GEMMs (bf16, split-K x3) -> combine + quantize ----
    dim3 gprep(96, 3);
    gemm_prep<<<gprep, 256, PRE_SMEM>>>(VcTh, VcTl, WqTh, WqTl, WcTh, WcTl, WkTh, WkTl,
                                        Woh, Wol, UcTh, UcTl, H);
    combine_quant<<<NBROWS, 256>>>(H, XtT, Bq1, Bq2, sB, Uq1, Uq2, sU);

    // ---- main: H = x @ Bp^T (int8 2-digit)  [8192, 1280] ----
    dim3 gH(NPROJ / 128, MTOT / 128);
    gemm_i8<false><<<gH, 512, I8_SMEM>>>(xq1, xq2, sx, Bq1, Bq2, sB,
                                         H, NPROJ, D_MODEL, nullptr);

    // ---- causal scan over H cols [512,1280) ----
    dim3 gs(SCANC / 128, NCH, BATCH);
    scan_partial<<<gs, 128>>>(H + 512, cs);
    scan_offsets<<<(BATCH * SCANC + 255) / 256, 256>>>(cs);

    // ---- fused apply + build G + quantize ----
    apply_build_q<<<MTOT, 256>>>(H, cs, alpha, Gq1, Gq2, sG);

    // ---- out = G @ UWo^T + bo (int8 2-digit)  [8192, 1024] ----
    dim3 gO(D_MODEL / 128, MTOT / 128);
    gemm_i8<true><<<gO, 512, I8_SMEM>>>(Gq1, Gq2, sG, Uq1, Uq2, sU,
                                        out, D_MODEL, R2, bo);
}

// round 10
// speedup vs baseline: 2.2809x; 2.2809x over previous
#include <cuda_runtime.h>
#include <cuda_bf16.h>
#include <cstdint>

// Problem constants (fixed shapes)
#define D_MODEL 1024
#define RANK    256
#define R2      (2*RANK)          // 512
#define NPROJ   (R2 + R2 + RANK)  // 1280 = [a_b|a_t | c_b|c_t | z]
#define BATCH   4
#define SEQ     2048
#define MTOT    (BATCH*SEQ)       // 8192
#define TCH     128
#define NCH     (SEQ/TCH)         // 16
#define SCANC   (R2 + RANK)       // 768 scanned columns
#define PSLICE  (1024*1024 + 1024*512)   // 1.5M floats per k-slice partial

// ---------------- scratch (device globals; no cudaMalloc allowed) ------------
__device__ float         g_H   [MTOT*NPROJ];   // reused as prep partial scratch first
__device__ __nv_bfloat16 g_xh  [MTOT*D_MODEL];
__device__ __nv_bfloat16 g_xl  [MTOT*D_MODEL];
__device__ __nv_bfloat16 g_Gh  [MTOT*R2];
__device__ __nv_bfloat16 g_Gl  [MTOT*R2];
__device__ __nv_bfloat16 g_Bph [NPROJ*D_MODEL];
__device__ __nv_bfloat16 g_Bpl [NPROJ*D_MODEL];
__device__ __nv_bfloat16 g_UWoh[D_MODEL*R2];
__device__ __nv_bfloat16 g_UWol[D_MODEL*R2];
__device__ __nv_bfloat16 g_WqTh[D_MODEL*D_MODEL], g_WqTl[D_MODEL*D_MODEL];
__device__ __nv_bfloat16 g_WkTh[D_MODEL*D_MODEL], g_WkTl[D_MODEL*D_MODEL];
__device__ __nv_bfloat16 g_VcTh[R2*D_MODEL],      g_VcTl[R2*D_MODEL];
__device__ __nv_bfloat16 g_WcTh[R2*D_MODEL],      g_WcTl[R2*D_MODEL];
__device__ __nv_bfloat16 g_UcTh[R2*D_MODEL],      g_UcTl[R2*D_MODEL];
__device__ __nv_bfloat16 g_Woh [D_MODEL*D_MODEL], g_Wol [D_MODEL*D_MODEL];
__device__ float g_bo [D_MODEL];
__device__ float g_cs [BATCH*NCH*SCANC];

// ====================== helpers ==============================================
#define LDSM_X4(R, A) \
    asm volatile("ldmatrix.sync.aligned.m8n8.x4.shared.b16 {%0,%1,%2,%3}, [%4];" \
        : "=r"((R)[0]), "=r"((R)[1]), "=r"((R)[2]), "=r"((R)[3]) : "r"(A))
#define MMA_BF16(D, Ar, Br) \
    asm volatile("mma.sync.aligned.m16n8k16.row.col.f32.bf16.bf16.f32 " \
        "{%0,%1,%2,%3}, {%4,%5,%6,%7}, {%8,%9}, {%0,%1,%2,%3};" \
        : "+f"((D)[0]), "+f"((D)[1]), "+f"((D)[2]), "+f"((D)[3]) \
        : "r"((Ar)[0]), "r"((Ar)[1]), "r"((Ar)[2]), "r"((Ar)[3]), \
          "r"((Br)[0]), "r"((Br)[1]))

__device__ __forceinline__ uint32_t smem_u32(const void* p) {
    uint32_t a;
    asm("{ .reg .u64 t; cvta.to.shared.u64 t, %1; cvt.u32.u64 %0, t; }" : "=r"(a) : "l"(p));
    return a;
}

// paired-row swizzled byte offset (64B logical rows in 128B physical rows)
__device__ __forceinline__ uint32_t swoff(int m, int c) {
    const int p  = m >> 1;
    const int cc = (((m & 1) << 2) | c) ^ (p & 7);
    return (uint32_t)(p * 128 + cc * 16);
}

__device__ __forceinline__ uint32_t pack2(__nv_bfloat16 x, __nv_bfloat16 y) {
    return (uint32_t)__bfloat16_as_ushort(x) | ((uint32_t)__bfloat16_as_ushort(y) << 16);
}

__device__ __forceinline__ void bf_split(float v, __nv_bfloat16& h, __nv_bfloat16& l) {
    h = __float2bfloat16(v);
    l = __float2bfloat16(v - __bfloat162float(h));
}

__device__ __forceinline__ void cpasync16(uint32_t dst, const void* src) {
    asm volatile("cp.async.cg.shared.global [%0], [%1], 16;" :: "r"(dst), "l"(src));
}
#define CP_COMMIT() asm volatile("cp.async.commit_group;" ::: "memory")
#define CP_WAIT1()  asm volatile("cp.async.wait_group 1;"  ::: "memory")
#define CP_WAIT2()  asm volatile("cp.async.wait_group 2;"  ::: "memory")

// ====================== bf16 GEMM core (prep path, proven R8) ================
#define TILE_B     8192
#define STAGE_B    32768
#define PRE_SMEM   (3*STAGE_B)   // 96 KB

__device__ __forceinline__ void gemm_core(
    const __nv_bfloat16* __restrict__ Ah_g, const __nv_bfloat16* __restrict__ Al_g,
    const __nv_bfloat16* __restrict__ Bh_g, const __nv_bfloat16* __restrict__ Bl_g,
    int K, int kbeg, int kend, long bm, long bn, uint32_t sb, float acc[4][4][4])
{
    const int tid  = threadIdx.x;
    const int wid  = tid >> 5, lane = tid & 31;
    const int warpM = wid & 1, warpN = wid >> 1;

    uint32_t offA0[2], offBx[2];
#pragma unroll
    for (int kg = 0; kg < 2; kg++) {
        offA0[kg] = swoff(warpM * 64 + (lane & 15), 2 * kg + (lane >> 4));
        offBx[kg] = swoff(warpN * 32 + ((lane >> 4) << 3) + (lane & 7),
                          2 * kg + ((lane >> 3) & 1));
    }

    const int mrow = tid >> 2, mc = tid & 3;
    const uint32_t so0 = swoff(mrow, mc), so1 = swoff(mrow + 64, mc);

    auto issue = [&](int kt) {
        const uint32_t base = sb + (uint32_t)(kt % 3) * STAGE_B;
        const long koff = (long)kt * 32 + mc * 8;
        const long gA0 = (bm + mrow) * (long)K + koff;
        const long gA1 = gA0 + 64L * K;
        const long gB0 = (bn + mrow) * (long)K + koff;
        const long gB1 = gB0 + 64L * K;
        cpasync16(base + so0,            Ah_g + gA0);
        cpasync16(base + so1,            Ah_g + gA1);
        cpasync16(base + TILE_B + so0,   Al_g + gA0);
        cpasync16(base + TILE_B + so1,   Al_g + gA1);
        cpasync16(base + 2*TILE_B + so0, Bh_g + gB0);
        cpasync16(base + 2*TILE_B + so1, Bh_g + gB1);
        cpasync16(base + 3*TILE_B + so0, Bl_g + gB0);
        cpasync16(base + 3*TILE_B + so1, Bl_g + gB1);
    };

    issue(kbeg);     CP_COMMIT();
    issue(kbeg + 1); CP_COMMIT();

#pragma unroll 1
    for (int kt = kbeg; kt < kend; kt++) {
        CP_WAIT1();
        __syncthreads();
        if (kt + 2 < kend) issue(kt + 2);
        CP_COMMIT();

        const uint32_t bb = sb + (uint32_t)(kt % 3) * STAGE_B;
#pragma unroll
        for (int kg = 0; kg < 2; kg++) {
            uint32_t bh[4][2], bl[4][2];
#pragma unroll
            for (int jp = 0; jp < 2; jp++) {
                uint32_t rh[4], rl[4];
                LDSM_X4(rh, bb + 2*TILE_B + offBx[kg] + (uint32_t)jp * 1024);
                LDSM_X4(rl, bb + 3*TILE_B + offBx[kg] + (uint32_t)jp * 1024);
                bh[2*jp][0]   = rh[0]; bh[2*jp][1]   = rh[1];
                bh[2*jp+1][0] = rh[2]; bh[2*jp+1][1] = rh[3];
                bl[2*jp][0]   = rl[0]; bl[2*jp][1]   = rl[1];
                bl[2*jp+1][0] = rl[2]; bl[2*jp+1][1] = rl[3];
            }
#pragma unroll
            for (int i = 0; i < 4; i++) {
                uint32_t ah[4], al[4];
                const uint32_t ao = bb + offA0[kg] + (uint32_t)i * 1024;
                LDSM_X4(ah, ao);
                LDSM_X4(al, ao + TILE_B);
#pragma unroll
                for (int j = 0; j < 4; j++) {
                    MMA_BF16(acc[i][j], ah, bh[j]);
                    MMA_BF16(acc[i][j], ah, bl[j]);
                    MMA_BF16(acc[i][j], al, bh[j]);
                }
            }
        }
    }
}

// ---------------- prep GEMM: compact tiles, split-K x3, fp32 partials --------
__global__ __launch_bounds__(256, 2)
void gemm_prep(const __nv_bfloat16* __restrict__ VcTh, const __nv_bfloat16* __restrict__ VcTl,
               const __nv_bfloat16* __restrict__ WqTh, const __nv_bfloat16* __restrict__ WqTl,
               const __nv_bfloat16* __restrict__ WcTh, const __nv_bfloat16* __restrict__ WcTl,
               const __nv_bfloat16* __restrict__ WkTh, const __nv_bfloat16* __restrict__ WkTl,
               const __nv_bfloat16* __restrict__ Woh,  const __nv_bfloat16* __restrict__ Wol,
               const __nv_bfloat16* __restrict__ UcTh, const __nv_bfloat16* __restrict__ UcTl,
               float* __restrict__ P)
{
    const int t = blockIdx.x, s = blockIdx.y;
    const __nv_bfloat16 *Ah, *Al, *Bh, *Bl;
    long bm, bn, ooff; int ldc;
    if (t < 32)      { Ah=VcTh; Al=VcTl; Bh=WqTh; Bl=WqTl; bm=(t>>3)*128;      bn=(t&7)*128;      ldc=1024; ooff=0; }
    else if (t < 64) { Ah=WcTh; Al=WcTl; Bh=WkTh; Bl=WkTl; bm=((t-32)>>3)*128; bn=((t-32)&7)*128; ldc=1024; ooff=512L*1024; }
    else             { Ah=Woh;  Al=Wol;  Bh=UcTh; Bl=UcTl; bm=((t-64)>>2)*128; bn=((t-64)&3)*128; ldc=512;  ooff=1024L*1024; }
    const int K = 1024;
    const int kbeg = s * 11, kend = (s == 2) ? 32 : kbeg + 11;
    float* Cp = P + (long)s * PSLICE + ooff;

    extern __shared__ __align__(128) char sm[];
    const uint32_t sb = smem_u32(sm);

    float acc[4][4][4];
#pragma unroll
    for (int i = 0; i < 4; i++)
#pragma unroll
        for (int j = 0; j < 4; j++)
#pragma unroll
            for (int q = 0; q < 4; q++) acc[i][j][q] = 0.f;

    gemm_core(Ah, Al, Bh, Bl, K, kbeg, kend, bm, bn, sb, acc);

    const int tid = threadIdx.x, wid = tid >> 5, lane = tid & 31;
    const int warpM = wid & 1, warpN = wid >> 1;
    const int g = lane >> 2, tg = lane & 3;
#pragma unroll
    for (int i = 0; i < 4; i++) {
        const long row = bm + warpM * 64 + i * 16 + g;
#pragma unroll
        for (int j = 0; j < 4; j++) {
            const int col = (int)bn + warpN * 32 + j * 8 + 2 * tg;
            *(float2*)(Cp + row * ldc + col)       = make_float2(acc[i][j][0], acc[i][j][1]);
            *(float2*)(Cp + (row + 8) * ldc + col) = make_float2(acc[i][j][2], acc[i][j][3]);
        }
    }
}

// combine 3 k-slice partials -> bf16 hi/lo planes
__global__ void combine_prep(const float* __restrict__ P,
                             __nv_bfloat16* __restrict__ Bph, __nv_bfloat16* __restrict__ Bpl,
                             __nv_bfloat16* __restrict__ UWoh, __nv_bfloat16* __restrict__ UWol)
{
    const long n = PSLICE;
    for (long i = (long)blockIdx.x * blockDim.x + threadIdx.x; i < n;
         i += (long)gridDim.x * blockDim.x) {
        const float v = P[i] + P[PSLICE + i] + P[2L*PSLICE + i];
        __nv_bfloat16 h, l;
        bf_split(v, h, l);
        if (i < 1024L * 1024) { Bph[i] = h; Bpl[i] = l; }
        else { UWoh[i - 1024L*1024] = h; UWol[i - 1024L*1024] = l; }
    }
}

// ====================== main GEMM: CTA 128x256, warp tile 64x64 ==============
// 8 warps (2M x 4N), BK=32, 4-stage cp.async, 192 KB smem, 1 CTA/SM.
// Stage layout: [Ah 8K][Al 8K][Bh 16K][Bl 16K] = 48 KB.
#define MA_TILE   8192
#define MB_TILE   16384
#define MSTAGE_B  49152
#define MAIN_SMEM (4*MSTAGE_B)   // 192 KB

template<bool BIAS>
__global__ __launch_bounds__(256, 1)
void gemm_main(const __nv_bfloat16* __restrict__ Ah_g, const __nv_bfloat16* __restrict__ Al_g,
               const __nv_bfloat16* __restrict__ Bh_g, const __nv_bfloat16* __restrict__ Bl_g,
               float* __restrict__ C, int N, int K, const float* __restrict__ bias)
{
    extern __shared__ __align__(128) char sm[];
    const uint32_t sb = smem_u32(sm);
    const int tid = threadIdx.x, wid = tid >> 5, lane = tid & 31;
    const int warpM = wid & 1, warpN = wid >> 1;     // 2 x 4
    const long bm = (long)blockIdx.y * 128, bn = (long)blockIdx.x * 256;

    uint32_t offA0[2], offB0[2];
#pragma unroll
    for (int kg = 0; kg < 2; kg++) {
        offA0[kg] = swoff(warpM * 64 + (lane & 15), 2 * kg + (lane >> 4));
        offB0[kg] = swoff(warpN * 64 + ((lane >> 4) << 3) + (lane & 7),
                          2 * kg + ((lane >> 3) & 1));
    }

    // cp.async: 3072 16B chunks/stage; rep 0-1 Ah, 2-3 Al, 4-7 Bh, 8-11 Bl
    auto issue = [&](int kt) {
        const uint32_t base = sb + (uint32_t)(kt & 3) * MSTAGE_B;
        const long kofs = (long)kt * 32;
#pragma unroll
        for (int rep = 0; rep < 12; rep++) {
            const int id = tid + 256 * rep;
            uint32_t poff; const __nv_bfloat16* src; int cid; long rowbase;
            if (rep < 2)      { poff = 0;                 src = Ah_g; cid = id;        rowbase = bm; }
            else if (rep < 4) { poff = MA_TILE;           src = Al_g; cid = id - 512;  rowbase = bm; }
            else if (rep < 8) { poff = 2*MA_TILE;         src = Bh_g; cid = id - 1024; rowbase = bn; }
            else              { poff = 2*MA_TILE+MB_TILE; src = Bl_g; cid = id - 2048; rowbase = bn; }
            const int m = cid >> 2, c = cid & 3;
            cpasync16(base + poff + swoff(m, c),
                      src + (rowbase + m) * (long)K + kofs + c * 8);
        }
    };

    float acc[4][8][4];
#pragma unroll
    for (int i = 0; i < 4; i++)
#pragma unroll
        for (int j = 0; j < 8; j++)
#pragma unroll
            for (int q = 0; q < 4; q++) acc[i][j][q] = 0.f;

    const int nk = K / 32;
    issue(0); CP_COMMIT();
    issue(1); CP_COMMIT();
    issue(2); CP_COMMIT();

#pragma unroll 1
    for (int kt = 0; kt < nk; kt++) {
        CP_WAIT2();
        __syncthreads();
        if (kt + 3 < nk) issue(kt + 3);
        CP_COMMIT();

        const uint32_t bb = sb + (uint32_t)(kt & 3) * MSTAGE_B;
#pragma unroll
        for (int kg = 0; kg < 2; kg++) {
            uint32_t bh[8][2], bl[8][2];
#pragma unroll
            for (int jp = 0; jp < 4; jp++) {
                uint32_t rh[4], rl[4];
                const uint32_t bo_ = offB0[kg] + (uint32_t)jp * 1024;
                LDSM_X4(rh, bb + 2*MA_TILE + bo_);
                LDSM_X4(rl, bb + 2*MA_TILE + MB_TILE + bo_);
                bh[2*jp][0]   = rh[0]; bh[2*jp][1]   = rh[1];
                bh[2*jp+1][0] = rh[2]; bh[2*jp+1][1] = rh[3];
                bl[2*jp][0]   = rl[0]; bl[2*jp][1]   = rl[1];
                bl[2*jp+1][0] = rl[2]; bl[2*jp+1][1] = rl[3];
            }
#pragma unroll
            for (int i = 0; i < 4; i++) {
                uint32_t ah[4], al[4];
                const uint32_t ao = bb + offA0[kg] + (uint32_t)i * 1024;
                LDSM_X4(ah, ao);
                LDSM_X4(al, ao + MA_TILE);
#pragma unroll
                for (int j = 0; j < 8; j++) {
                    MMA_BF16(acc[i][j], ah, bh[j]);
                    MMA_BF16(acc[i][j], ah, bl[j]);
                    MMA_BF16(acc[i][j], al, bh[j]);
                }
            }
        }
    }

    const int g = lane >> 2, tg = lane & 3;
#pragma unroll
    for (int i = 0; i < 4; i++) {
        const long row = bm + warpM * 64 + i * 16 + g;
#pragma unroll
        for (int j = 0; j < 8; j++) {
            const int col = (int)bn + warpN * 64 + j * 8 + 2 * tg;
            float b0 = 0.f, b1 = 0.f;
            if (BIAS) { b0 = bias[col]; b1 = bias[col + 1]; }
            float2 v0 = make_float2(acc[i][j][0] + b0, acc[i][j][1] + b1);
            float2 v1 = make_float2(acc[i][j][2] + b0, acc[i][j][3] + b1);
            *(float2*)(C + row * N + col)       = v0;
            *(float2*)(C + (row + 8) * N + col) = v1;
        }
    }
}

// ====================== batched transpose / concat / split ===================
__global__ void trans_batched(const float* __restrict__ Wq, const float* __restrict__ Wk,
                              const float* __restrict__ V_b, const float* __restrict__ V_t,
                              const float* __restrict__ W_b, const float* __restrict__ W_t,
                              const float* __restrict__ U_b, const float* __restrict__ U_t,
                              const float* __restrict__ X_t, const float* __restrict__ Wo,
                              __nv_bfloat16* __restrict__ WqTh, __nv_bfloat16* __restrict__ WqTl,
                              __nv_bfloat16* __restrict__ WkTh, __nv_bfloat16* __restrict__ WkTl,
                              __nv_bfloat16* __restrict__ VcTh, __nv_bfloat16* __restrict__ VcTl,
                              __nv_bfloat16* __restrict__ WcTh, __nv_bfloat16* __restrict__ WcTl,
                              __nv_bfloat16* __restrict__ UcTh, __nv_bfloat16* __restrict__ UcTl,
                              __nv_bfloat16* __restrict__ Bph,  __nv_bfloat16* __restrict__ Bpl,
                              __nv_bfloat16* __restrict__ Woh,  __nv_bfloat16* __restrict__ Wol)
{
    __shared__ float t[32][33];
    const int z = blockIdx.z;
    const int bx = blockIdx.x, by = blockIdx.y;
    const int tx = threadIdx.x, ty = threadIdx.y;

    if (z == 9) {
#pragma unroll
        for (int j = 0; j < 32; j += 8) {
            const long o = (long)(by * 32 + ty + j) * 1024 + bx * 32 + tx;
            __nv_bfloat16 h, l;
            bf_split(Wo[o], h, l);
            Woh[o] = h; Wol[o] = l;
        }
        return;
    }

    const float* src; int Cin;
    __nv_bfloat16 *Dh, *Dl; int roff = 0;
    switch (z) {
        case 0: src = Wq;  Cin = 1024; Dh = WqTh; Dl = WqTl; break;
        case 1: src = Wk;  Cin = 1024; Dh = WkTh; Dl = WkTl; break;
        case 2: src = V_b; Cin = 256;  Dh = VcTh; Dl = VcTl; roff = 0;    break;
        case 3: src = V_t; Cin = 256;  Dh = VcTh; Dl = VcTl; roff = 256;  break;
        case 4: src = W_b; Cin = 256;  Dh = WcTh; Dl = WcTl; roff = 0;    break;
        case 5: src = W_t; Cin = 256;  Dh = WcTh; Dl = WcTl; roff = 256;  break;
        case 6: src = U_b; Cin = 256;  Dh = UcTh; Dl = UcTl; roff = 0;    break;
        case 7: src = U_t; Cin = 256;  Dh = UcTh; Dl = UcTl; roff = 256;  break;
        default: src = X_t; Cin = 256; Dh = Bph;  Dl = Bpl;  roff = 1024; break;
    }
    if (Cin == 256 && bx >= 8) return;
#pragma unroll
    for (int j = 0; j < 32; j += 8)
        t[ty + j][tx] = src[(long)(by * 32 + ty + j) * Cin + bx * 32 + tx];
    __syncthreads();
#pragma unroll
    for (int j = 0; j < 32; j += 8) {
        __nv_bfloat16 h, l;
        bf_split(t[tx][ty + j], h, l);
        const long o = (long)(roff + bx * 32 + ty + j) * 1024 + by * 32 + tx;
        Dh[o] = h; Dl[o] = l;
    }
}

// ---------------- split x into bf16 hi/lo planes -----------------------------
__global__ void split_x(const float* __restrict__ x,
                        __nv_bfloat16* __restrict__ xh, __nv_bfloat16* __restrict__ xl)
{
    const long n4 = (long)MTOT * D_MODEL / 4;
    for (long i = (long)blockIdx.x * blockDim.x + threadIdx.x; i < n4;
         i += (long)gridDim.x * blockDim.x) {
        float4 v = ((const float4*)x)[i];
        __nv_bfloat16 h[4], l[4];
        bf_split(v.x, h[0], l[0]); bf_split(v.y, h[1], l[1]);
        bf_split(v.z, h[2], l[2]); bf_split(v.w, h[3], l[3]);
        uint2 H, L;
        H.x = pack2(h[0], h[1]); H.y = pack2(h[2], h[3]);
        L.x = pack2(l[0], l[1]); L.y = pack2(l[2], l[3]);
        ((uint2*)xh)[i] = H;
        ((uint2*)xl)[i] = L;
    }
}

// ---------------- causal cumulative scan (cols 512..1280 of H) --------------
__global__ void scan_partial(float* __restrict__ Hc, float* __restrict__ cs)
{
    const int col = blockIdx.x * 128 + threadIdx.x;   // 0..767
    const int ch  = blockIdx.y;
    const int b   = blockIdx.z;
    const long base = ((long)b * SEQ + (long)ch * TCH) * NPROJ + col;
    float run = 0.f;
    for (int t = 0; t < TCH; t++) {
        run += Hc[base + (long)t * NPROJ];
        Hc[base + (long)t * NPROJ] = run;
    }
    cs[((long)b * NCH + ch) * SCANC + col] = run;
}

__global__ void scan_offsets(float* __restrict__ cs)
{
    const int i = blockIdx.x * blockDim.x + threadIdx.x;
    if (i >= BATCH * SCANC) return;
    const int b = i / SCANC, col = i % SCANC;
    float off = 0.f;
    for (int ch = 0; ch < NCH; ch++) {
        const long idx = ((long)b * NCH + ch) * SCANC + col;
        const float v = cs[idx];
        cs[idx] = off;
        off += v;
    }
}

// ---------------- fused scan-apply + G build (bf16 split output) -------------
__global__ void apply_build(const float* __restrict__ H, const float* __restrict__ cs,
                            const float* __restrict__ alpha,
                            __nv_bfloat16* __restrict__ Gh, __nv_bfloat16* __restrict__ Gl)
{
    const int i = blockIdx.x * blockDim.x + threadIdx.x;
    if (i >= MTOT * RANK) return;
    const int m = i / RANK, r = i % RANK;
    const int t = m % SEQ, b = m / SEQ, ch = t / TCH;
    const float inv = 1.0f / (float)(t + 1);
    const float* hrow = H + (long)m * NPROJ;
    const float* co = cs + ((long)b * NCH + ch) * SCANC;
    const float cb = hrow[512 + r]  + co[r];
    const float ct = hrow[768 + r]  + co[256 + r];
    const float z  = (hrow[1024 + r] + co[512 + r]) * inv;
    const float gb = hrow[r] * cb * inv;
    const float gt = alpha[0] * hrow[256 + r] * z * ct * inv;
    const long o = (long)m * R2 + r;
    __nv_bfloat16 h, l;
    bf_split(gb, h, l); Gh[o] = h;        Gl[o] = l;
    bf_split(gt, h, l); Gh[o + RANK] = h; Gl[o + RANK] = l;
}

// bo[d] = sum_e Wo[d,e] * (bias_b[e] + alpha*bias_t[e])
__global__ void bo_kernel(const float* __restrict__ Wo, const float* __restrict__ bb,
                          const float* __restrict__ bt, const float* __restrict__ alpha,
                          float* __restrict__ bo)
{
    const int w = (blockIdx.x * blockDim.x + threadIdx.x) >> 5;
    const int lane = threadIdx.x & 31;
    if (w >= D_MODEL) return;
    const float a = alpha[0];
    float s = 0.f;
    for (int e = lane; e < D_MODEL; e += 32)
        s += Wo[(long)w * D_MODEL + e] * (bb[e] + a * bt[e]);
#pragma unroll
    for (int o = 16; o; o >>= 1) s += __shfl_xor_sync(0xFFFFFFFFu, s, o);
    if (lane == 0) bo[w] = s;
}

// ---------------- launch ------------------------------------------------------
extern "C" void kernel_launch(void* const* d_in, const int* in_sizes, int n_in,
                              void* d_out, int out_size)
{
    const float* x      = (const float*)d_in[0];
    const float* Wq     = (const float*)d_in[1];
    const float* Wk     = (const float*)d_in[2];
    const float* Wo     = (const float*)d_in[3];
    const float* U_b    = (const float*)d_in[4];
    const float* V_b    = (const float*)d_in[5];
    const float* W_b    = (const float*)d_in[6];
    const float* bias_b = (const float*)d_in[7];
    const float* U_t    = (const float*)d_in[8];
    const float* V_t    = (const float*)d_in[9];
    const float* W_t    = (const float*)d_in[10];
    const float* X_t    = (const float*)d_in[11];
    const float* bias_t = (const float*)d_in[12];
    const float* alpha  = (const float*)d_in[13];
    float* out = (float*)d_out;

    float *H, *bo, *cs;
    __nv_bfloat16 *xh, *xl, *Gh, *Gl, *Bph, *Bpl, *UWoh, *UWol;
    __nv_bfloat16 *WqTh, *WqTl, *WkTh, *WkTl, *VcTh, *VcTl, *WcTh, *WcTl, *UcTh, *UcTl, *Woh, *Wol;
    cudaGetSymbolAddress((void**)&H,    g_H);
    cudaGetSymbolAddress((void**)&xh,   g_xh);
    cudaGetSymbolAddress((void**)&xl,   g_xl);
    cudaGetSymbolAddress((void**)&Gh,   g_Gh);
    cudaGetSymbolAddress((void**)&Gl,   g_Gl);
    cudaGetSymbolAddress((void**)&Bph,  g_Bph);
    cudaGetSymbolAddress((void**)&Bpl,  g_Bpl);
    cudaGetSymbolAddress((void**)&UWoh, g_UWoh);
    cudaGetSymbolAddress((void**)&UWol, g_UWol);
    cudaGetSymbolAddress((void**)&WqTh, g_WqTh);
    cudaGetSymbolAddress((void**)&WqTl, g_WqTl);
    cudaGetSymbolAddress((void**)&WkTh, g_WkTh);
    cudaGetSymbolAddress((void**)&WkTl, g_WkTl);
    cudaGetSymbolAddress((void**)&VcTh, g_VcTh);
    cudaGetSymbolAddress((void**)&VcTl, g_VcTl);
    cudaGetSymbolAddress((void**)&WcTh, g_WcTh);
    cudaGetSymbolAddress((void**)&WcTl, g_WcTl);
    cudaGetSymbolAddress((void**)&UcTh, g_UcTh);
    cudaGetSymbolAddress((void**)&UcTl, g_UcTl);
    cudaGetSymbolAddress((void**)&Woh,  g_Woh);
    cudaGetSymbolAddress((void**)&Wol,  g_Wol);
    cudaGetSymbolAddress((void**)&bo,   g_bo);
    cudaGetSymbolAddress((void**)&cs,   g_cs);

    cudaFuncSetAttribute(gemm_prep,        cudaFuncAttributeMaxDynamicSharedMemorySize, PRE_SMEM);
    cudaFuncSetAttribute(gemm_main<false>, cudaFuncAttributeMaxDynamicSharedMemorySize, MAIN_SMEM);
    cudaFuncSetAttribute(gemm_main<true>,  cudaFuncAttributeMaxDynamicSharedMemorySize, MAIN_SMEM);

    // ---- prep: transposes/concats + bias fold + x split ----
    dim3 tgrid(32, 32, 10), tblk(32, 8);
    trans_batched<<<tgrid, tblk>>>(Wq, Wk, V_b, V_t, W_b, W_t, U_b, U_t, X_t, Wo,
                                   WqTh, WqTl, WkTh, WkTl, VcTh, VcTl, WcTh, WcTl,
                                   UcTh, UcTl, Bph, Bpl, Woh, Wol);
    bo_kernel<<<128, 256>>>(Wo, bias_b, bias_t, alpha, bo);
    split_x<<<4096, 256>>>(x, xh, xl);

    // ---- prep GEMMs: 96 tiles x 3 k-slices = 288 CTAs (one full wave) ----
    dim3 gprep(96, 3);
    gemm_prep<<<gprep, 256, PRE_SMEM>>>(VcTh, VcTl, WqTh, WqTl, WcTh, WcTl, WkTh, WkTl,
                                        Woh, Wol, UcTh, UcTl, H);
    combine_prep<<<1024, 256>>>(H, Bph, Bpl, UWoh, UWol);

    // ---- main: H = x @ Bp^T  [8192, 1280] ----
    dim3 gH(NPROJ / 256, MTOT / 128);
    gemm_main<false><<<gH, 256, MAIN_SMEM>>>(xh, xl, Bph, Bpl, H, NPROJ, D_MODEL, nullptr);

    // ---- causal scan over H cols [512,1280) ----
    dim3 gs(SCANC / 128, NCH, BATCH);
    scan_partial<<<gs, 128>>>(H + 512, cs);
    scan_offsets<<<(BATCH * SCANC + 255) / 256, 256>>>(cs);

    // ---- fused apply + build G (bf16 split) ----
    apply_build<<<(MTOT * RANK + 255) / 256, 256>>>(H, cs, alpha, Gh, Gl);

    // ---- out = G @ UWo^T + bo  [8192, 1024] ----
    dim3 gO(D_MODEL / 256, MTOT / 128);
    gemm_main<true><<<gO, 256, MAIN_SMEM>>>(Gh, Gl, UWoh, UWol, out, D_MODEL, R2, bo);
}

// round 11
// speedup vs baseline: 2.5887x; 1.1350x over previous
#include <cuda_runtime.h>
#include <cuda_bf16.h>
#include <cstdint>

// Problem constants (fixed shapes)
#define D_MODEL 1024
#define RANK    256
#define R2      (2*RANK)          // 512
#define NPROJ   (R2 + R2 + RANK)  // 1280 = [a_b|a_t | c_b|c_t | z]
#define BATCH   4
#define SEQ     2048
#define MTOT    (BATCH*SEQ)       // 8192
#define TCH     128
#define NCH     (SEQ/TCH)         // 16
#define SCANC   (R2 + RANK)       // 768 scanned columns
#define PSLICE  (1024*1024 + 1024*512)   // 1.5M floats per k-slice partial

// ---------------- scratch (device globals; no cudaMalloc allowed) ------------
__device__ float         g_H   [MTOT*NPROJ];   // reused as prep partial scratch first
__device__ __nv_bfloat16 g_xh  [MTOT*D_MODEL];
__device__ __nv_bfloat16 g_xl  [MTOT*D_MODEL];
__device__ __nv_bfloat16 g_Gh  [MTOT*R2];
__device__ __nv_bfloat16 g_Gl  [MTOT*R2];
__device__ __nv_bfloat16 g_Bph [NPROJ*D_MODEL];
__device__ __nv_bfloat16 g_Bpl [NPROJ*D_MODEL];
__device__ __nv_bfloat16 g_UWoh[D_MODEL*R2];
__device__ __nv_bfloat16 g_UWol[D_MODEL*R2];
__device__ __nv_bfloat16 g_WqTh[D_MODEL*D_MODEL], g_WqTl[D_MODEL*D_MODEL];
__device__ __nv_bfloat16 g_WkTh[D_MODEL*D_MODEL], g_WkTl[D_MODEL*D_MODEL];
__device__ __nv_bfloat16 g_VcTh[R2*D_MODEL],      g_VcTl[R2*D_MODEL];
__device__ __nv_bfloat16 g_WcTh[R2*D_MODEL],      g_WcTl[R2*D_MODEL];
__device__ __nv_bfloat16 g_UcTh[R2*D_MODEL],      g_UcTl[R2*D_MODEL];
__device__ __nv_bfloat16 g_Woh [D_MODEL*D_MODEL], g_Wol [D_MODEL*D_MODEL];
__device__ float g_bo [D_MODEL];
__device__ float g_cs [BATCH*NCH*SCANC];

// ====================== helpers ==============================================
#define LDSM_X4(R, A) \
    asm volatile("ldmatrix.sync.aligned.m8n8.x4.shared.b16 {%0,%1,%2,%3}, [%4];" \
        : "=r"((R)[0]), "=r"((R)[1]), "=r"((R)[2]), "=r"((R)[3]) : "r"(A))
#define MMA_BF16(D, Ar, Br) \
    asm volatile("mma.sync.aligned.m16n8k16.row.col.f32.bf16.bf16.f32 " \
        "{%0,%1,%2,%3}, {%4,%5,%6,%7}, {%8,%9}, {%0,%1,%2,%3};" \
        : "+f"((D)[0]), "+f"((D)[1]), "+f"((D)[2]), "+f"((D)[3]) \
        : "r"((Ar)[0]), "r"((Ar)[1]), "r"((Ar)[2]), "r"((Ar)[3]), \
          "r"((Br)[0]), "r"((Br)[1]))

__device__ __forceinline__ uint32_t smem_u32(const void* p) {
    uint32_t a;
    asm("{ .reg .u64 t; cvta.to.shared.u64 t, %1; cvt.u32.u64 %0, t; }" : "=r"(a) : "l"(p));
    return a;
}

// paired-row swizzled byte offset (64B logical rows in 128B physical rows)
__device__ __forceinline__ uint32_t swoff(int m, int c) {
    const int p  = m >> 1;
    const int cc = (((m & 1) << 2) | c) ^ (p & 7);
    return (uint32_t)(p * 128 + cc * 16);
}

__device__ __forceinline__ uint32_t pack2(__nv_bfloat16 x, __nv_bfloat16 y) {
    return (uint32_t)__bfloat16_as_ushort(x) | ((uint32_t)__bfloat16_as_ushort(y) << 16);
}

__device__ __forceinline__ void bf_split(float v, __nv_bfloat16& h, __nv_bfloat16& l) {
    h = __float2bfloat16(v);
    l = __float2bfloat16(v - __bfloat162float(h));
}

__device__ __forceinline__ void cpasync16(uint32_t dst, const void* src) {
    asm volatile("cp.async.cg.shared.global [%0], [%1], 16;" :: "r"(dst), "l"(src));
}
#define CP_COMMIT() asm volatile("cp.async.commit_group;" ::: "memory")
#define CP_WAIT1()  asm volatile("cp.async.wait_group 1;"  ::: "memory")

// ====================== bf16 GEMM core (prep path, proven R8) ================
#define TILE_B     8192
#define STAGE_B    32768
#define PRE_SMEM   (3*STAGE_B)   // 96 KB

__device__ __forceinline__ void gemm_core(
    const __nv_bfloat16* __restrict__ Ah_g, const __nv_bfloat16* __restrict__ Al_g,
    const __nv_bfloat16* __restrict__ Bh_g, const __nv_bfloat16* __restrict__ Bl_g,
    int K, int kbeg, int kend, long bm, long bn, uint32_t sb, float acc[4][4][4])
{
    const int tid  = threadIdx.x;
    const int wid  = tid >> 5, lane = tid & 31;
    const int warpM = wid & 1, warpN = wid >> 1;

    uint32_t offA0[2], offBx[2];
#pragma unroll
    for (int kg = 0; kg < 2; kg++) {
        offA0[kg] = swoff(warpM * 64 + (lane & 15), 2 * kg + (lane >> 4));
        offBx[kg] = swoff(warpN * 32 + ((lane >> 4) << 3) + (lane & 7),
                          2 * kg + ((lane >> 3) & 1));
    }

    const int mrow = tid >> 2, mc = tid & 3;
    const uint32_t so0 = swoff(mrow, mc), so1 = swoff(mrow + 64, mc);

    auto issue = [&](int kt) {
        const uint32_t base = sb + (uint32_t)(kt % 3) * STAGE_B;
        const long koff = (long)kt * 32 + mc * 8;
        const long gA0 = (bm + mrow) * (long)K + koff;
        const long gA1 = gA0 + 64L * K;
        const long gB0 = (bn + mrow) * (long)K + koff;
        const long gB1 = gB0 + 64L * K;
        cpasync16(base + so0,            Ah_g + gA0);
        cpasync16(base + so1,            Ah_g + gA1);
        cpasync16(base + TILE_B + so0,   Al_g + gA0);
        cpasync16(base + TILE_B + so1,   Al_g + gA1);
        cpasync16(base + 2*TILE_B + so0, Bh_g + gB0);
        cpasync16(base + 2*TILE_B + so1, Bh_g + gB1);
        cpasync16(base + 3*TILE_B + so0, Bl_g + gB0);
        cpasync16(base + 3*TILE_B + so1, Bl_g + gB1);
    };

    issue(kbeg);     CP_COMMIT();
    issue(kbeg + 1); CP_COMMIT();

#pragma unroll 1
    for (int kt = kbeg; kt < kend; kt++) {
        CP_WAIT1();
        __syncthreads();
        if (kt + 2 < kend) issue(kt + 2);
        CP_COMMIT();

        const uint32_t bb = sb + (uint32_t)(kt % 3) * STAGE_B;
#pragma unroll
        for (int kg = 0; kg < 2; kg++) {
            uint32_t bh[4][2], bl[4][2];
#pragma unroll
            for (int jp = 0; jp < 2; jp++) {
                uint32_t rh[4], rl[4];
                LDSM_X4(rh, bb + 2*TILE_B + offBx[kg] + (uint32_t)jp * 1024);
                LDSM_X4(rl, bb + 3*TILE_B + offBx[kg] + (uint32_t)jp * 1024);
                bh[2*jp][0]   = rh[0]; bh[2*jp][1]   = rh[1];
                bh[2*jp+1][0] = rh[2]; bh[2*jp+1][1] = rh[3];
                bl[2*jp][0]   = rl[0]; bl[2*jp][1]   = rl[1];
                bl[2*jp+1][0] = rl[2]; bl[2*jp+1][1] = rl[3];
            }
#pragma unroll
            for (int i = 0; i < 4; i++) {
                uint32_t ah[4], al[4];
                const uint32_t ao = bb + offA0[kg] + (uint32_t)i * 1024;
                LDSM_X4(ah, ao);
                LDSM_X4(al, ao + TILE_B);
#pragma unroll
                for (int j = 0; j < 4; j++) {
                    MMA_BF16(acc[i][j], ah, bh[j]);
                    MMA_BF16(acc[i][j], ah, bl[j]);
                    MMA_BF16(acc[i][j], al, bh[j]);
                }
            }
        }
    }
}

// ---------------- prep GEMM: compact tiles, split-K x3, fp32 partials --------
__global__ __launch_bounds__(256, 2)
void gemm_prep(const __nv_bfloat16* __restrict__ VcTh, const __nv_bfloat16* __restrict__ VcTl,
               const __nv_bfloat16* __restrict__ WqTh, const __nv_bfloat16* __restrict__ WqTl,
               const __nv_bfloat16* __restrict__ WcTh, const __nv_bfloat16* __restrict__ WcTl,
               const __nv_bfloat16* __restrict__ WkTh, const __nv_bfloat16* __restrict__ WkTl,
               const __nv_bfloat16* __restrict__ Woh,  const __nv_bfloat16* __restrict__ Wol,
               const __nv_bfloat16* __restrict__ UcTh, const __nv_bfloat16* __restrict__ UcTl,
               float* __restrict__ P)
{
    const int t = blockIdx.x, s = blockIdx.y;
    const __nv_bfloat16 *Ah, *Al, *Bh, *Bl;
    long bm, bn, ooff; int ldc;
    if (t < 32)      { Ah=VcTh; Al=VcTl; Bh=WqTh; Bl=WqTl; bm=(t>>3)*128;      bn=(t&7)*128;      ldc=1024; ooff=0; }
    else if (t < 64) { Ah=WcTh; Al=WcTl; Bh=WkTh; Bl=WkTl; bm=((t-32)>>3)*128; bn=((t-32)&7)*128; ldc=1024; ooff=512L*1024; }
    else             { Ah=Woh;  Al=Wol;  Bh=UcTh; Bl=UcTl; bm=((t-64)>>2)*128; bn=((t-64)&3)*128; ldc=512;  ooff=1024L*1024; }
    const int K = 1024;
    const int kbeg = s * 11, kend = (s == 2) ? 32 : kbeg + 11;
    float* Cp = P + (long)s * PSLICE + ooff;

    extern __shared__ __align__(128) char sm[];
    const uint32_t sb = smem_u32(sm);

    float acc[4][4][4];
#pragma unroll
    for (int i = 0; i < 4; i++)
#pragma unroll
        for (int j = 0; j < 4; j++)
#pragma unroll
            for (int q = 0; q < 4; q++) acc[i][j][q] = 0.f;

    gemm_core(Ah, Al, Bh, Bl, K, kbeg, kend, bm, bn, sb, acc);

    const int tid = threadIdx.x, wid = tid >> 5, lane = tid & 31;
    const int warpM = wid & 1, warpN = wid >> 1;
    const int g = lane >> 2, tg = lane & 3;
#pragma unroll
    for (int i = 0; i < 4; i++) {
        const long row = bm + warpM * 64 + i * 16 + g;
#pragma unroll
        for (int j = 0; j < 4; j++) {
            const int col = (int)bn + warpN * 32 + j * 8 + 2 * tg;
            *(float2*)(Cp + row * ldc + col)       = make_float2(acc[i][j][0], acc[i][j][1]);
            *(float2*)(Cp + (row + 8) * ldc + col) = make_float2(acc[i][j][2], acc[i][j][3]);
        }
    }
}

// combine 3 k-slice partials -> bf16 hi/lo planes
__global__ void combine_prep(const float* __restrict__ P,
                             __nv_bfloat16* __restrict__ Bph, __nv_bfloat16* __restrict__ Bpl,
                             __nv_bfloat16* __restrict__ UWoh, __nv_bfloat16* __restrict__ UWol)
{
    const long n = PSLICE;
    for (long i = (long)blockIdx.x * blockDim.x + threadIdx.x; i < n;
         i += (long)gridDim.x * blockDim.x) {
        const float v = P[i] + P[PSLICE + i] + P[2L*PSLICE + i];
        __nv_bfloat16 h, l;
        bf_split(v, h, l);
        if (i < 1024L * 1024) { Bph[i] = h; Bpl[i] = l; }
        else { UWoh[i - 1024L*1024] = h; UWol[i - 1024L*1024] = l; }
    }
}

// ====================== main GEMM: 128x128 CTA, 4 warps, 64x64 warp tile =====
// 128 threads, BK=32, 3-stage cp.async (96 KB), 2 CTAs/SM.
// Per warp per k-iter: 32 LDSM.x4 feed 192 MMAs (6:1) — MMA-bound by design.
template<bool BIAS>
__global__ __launch_bounds__(128, 2)
void gemm_main(const __nv_bfloat16* __restrict__ Ah_g, const __nv_bfloat16* __restrict__ Al_g,
               const __nv_bfloat16* __restrict__ Bh_g, const __nv_bfloat16* __restrict__ Bl_g,
               float* __restrict__ C, int N, int K, const float* __restrict__ bias)
{
    extern __shared__ __align__(128) char sm[];
    const uint32_t sb = smem_u32(sm);
    const int tid = threadIdx.x, wid = tid >> 5, lane = tid & 31;
    const int warpM = wid & 1, warpN = wid >> 1;      // 2 x 2, 64x64 tiles
    const long bm = (long)blockIdx.y * 128, bn = (long)blockIdx.x * 128;

    uint32_t offA0[2], offB0[2];
#pragma unroll
    for (int kg = 0; kg < 2; kg++) {
        offA0[kg] = swoff(warpM * 64 + (lane & 15), 2 * kg + (lane >> 4));
        offB0[kg] = swoff(warpN * 64 + ((lane >> 4) << 3) + (lane & 7),
                          2 * kg + ((lane >> 3) & 1));
    }

    // cp.async: 2048 chunks/stage, 128 threads -> 16 per thread
    const int mrow = tid >> 2, mc = tid & 3;   // rows 0..31, chunks 0..3
    uint32_t soA[4];
#pragma unroll
    for (int rep = 0; rep < 4; rep++) soA[rep] = swoff(mrow + 32 * rep, mc);

    auto issue = [&](int kt) {
        const uint32_t base = sb + (uint32_t)(kt % 3) * STAGE_B;
        const long koff = (long)kt * 32 + mc * 8;
#pragma unroll
        for (int rep = 0; rep < 4; rep++) {
            const long gA = (bm + mrow + 32 * rep) * (long)K + koff;
            const long gB = (bn + mrow + 32 * rep) * (long)K + koff;
            cpasync16(base + soA[rep],            Ah_g + gA);
            cpasync16(base + TILE_B + soA[rep],   Al_g + gA);
            cpasync16(base + 2*TILE_B + soA[rep], Bh_g + gB);
            cpasync16(base + 3*TILE_B + soA[rep], Bl_g + gB);
        }
    };

    float acc[4][8][4];
#pragma unroll
    for (int i = 0; i < 4; i++)
#pragma unroll
        for (int j = 0; j < 8; j++)
#pragma unroll
            for (int q = 0; q < 4; q++) acc[i][j][q] = 0.f;

    const int nk = K / 32;
    issue(0); CP_COMMIT();
    issue(1); CP_COMMIT();

#pragma unroll 1
    for (int kt = 0; kt < nk; kt++) {
        CP_WAIT1();
        __syncthreads();
        if (kt + 2 < nk) issue(kt + 2);
        CP_COMMIT();

        const uint32_t bb = sb + (uint32_t)(kt % 3) * STAGE_B;
#pragma unroll
        for (int kg = 0; kg < 2; kg++) {
            uint32_t bh[8][2], bl[8][2];
#pragma unroll
            for (int jp = 0; jp < 4; jp++) {
                uint32_t rh[4], rl[4];
                const uint32_t bo_ = offB0[kg] + (uint32_t)jp * 1024;
                LDSM_X4(rh, bb + 2*TILE_B + bo_);
                LDSM_X4(rl, bb + 3*TILE_B + bo_);
                bh[2*jp][0]   = rh[0]; bh[2*jp][1]   = rh[1];
                bh[2*jp+1][0] = rh[2]; bh[2*jp+1][1] = rh[3];
                bl[2*jp][0]   = rl[0]; bl[2*jp][1]   = rl[1];
                bl[2*jp+1][0] = rl[2]; bl[2*jp+1][1] = rl[3];
            }
#pragma unroll
            for (int i = 0; i < 4; i++) {
                uint32_t ah[4], al[4];
                const uint32_t ao = bb + offA0[kg] + (uint32_t)i * 1024;
                LDSM_X4(ah, ao);
                LDSM_X4(al, ao + TILE_B);
#pragma unroll
                for (int j = 0; j < 8; j++) {
                    MMA_BF16(acc[i][j], ah, bh[j]);
                    MMA_BF16(acc[i][j], ah, bl[j]);
                    MMA_BF16(acc[i][j], al, bh[j]);
                }
            }
        }
    }

    const int g = lane >> 2, tg = lane & 3;
#pragma unroll
    for (int i = 0; i < 4; i++) {
        const long row = bm + warpM * 64 + i * 16 + g;
#pragma unroll
        for (int j = 0; j < 8; j++) {
            const int col = (int)bn + warpN * 64 + j * 8 + 2 * tg;
            float b0 = 0.f, b1 = 0.f;
            if (BIAS) { b0 = bias[col]; b1 = bias[col + 1]; }
            float2 v0 = make_float2(acc[i][j][0] + b0, acc[i][j][1] + b1);
            float2 v1 = make_float2(acc[i][j][2] + b0, acc[i][j][3] + b1);
            *(float2*)(C + row * N + col)       = v0;
            *(float2*)(C + (row + 8) * N + col) = v1;
        }
    }
}

// ====================== batched transpose / concat / split ===================
__global__ void trans_batched(const float* __restrict__ Wq, const float* __restrict__ Wk,
                              const float* __restrict__ V_b, const float* __restrict__ V_t,
                              const float* __restrict__ W_b, const float* __restrict__ W_t,
                              const float* __restrict__ U_b, const float* __restrict__ U_t,
                              const float* __restrict__ X_t, const float* __restrict__ Wo,
                              __nv_bfloat16* __restrict__ WqTh, __nv_bfloat16* __restrict__ WqTl,
                              __nv_bfloat16* __restrict__ WkTh, __nv_bfloat16* __restrict__ WkTl,
                              __nv_bfloat16* __restrict__ VcTh, __nv_bfloat16* __restrict__ VcTl,
                              __nv_bfloat16* __restrict__ WcTh, __nv_bfloat16* __restrict__ WcTl,
                              __nv_bfloat16* __restrict__ UcTh, __nv_bfloat16* __restrict__ UcTl,
                              __nv_bfloat16* __restrict__ Bph,  __nv_bfloat16* __restrict__ Bpl,
                              __nv_bfloat16* __restrict__ Woh,  __nv_bfloat16* __restrict__ Wol)
{
    __shared__ float t[32][33];
    const int z = blockIdx.z;
    const int bx = blockIdx.x, by = blockIdx.y;
    const int tx = threadIdx.x, ty = threadIdx.y;

    if (z == 9) {
#pragma unroll
        for (int j = 0; j < 32; j += 8) {
            const long o = (long)(by * 32 + ty + j) * 1024 + bx * 32 + tx;
            __nv_bfloat16 h, l;
            bf_split(Wo[o], h, l);
            Woh[o] = h; Wol[o] = l;
        }
        return;
    }

    const float* src; int Cin;
    __nv_bfloat16 *Dh, *Dl; int roff = 0;
    switch (z) {
        case 0: src = Wq;  Cin = 1024; Dh = WqTh; Dl = WqTl; break;
        case 1: src = Wk;  Cin = 1024; Dh = WkTh; Dl = WkTl; break;
        case 2: src = V_b; Cin = 256;  Dh = VcTh; Dl = VcTl; roff = 0;    break;
        case 3: src = V_t; Cin = 256;  Dh = VcTh; Dl = VcTl; roff = 256;  break;
        case 4: src = W_b; Cin = 256;  Dh = WcTh; Dl = WcTl; roff = 0;    break;
        case 5: src = W_t; Cin = 256;  Dh = WcTh; Dl = WcTl; roff = 256;  break;
        case 6: src = U_b; Cin = 256;  Dh = UcTh; Dl = UcTl; roff = 0;    break;
        case 7: src = U_t; Cin = 256;  Dh = UcTh; Dl = UcTl; roff = 256;  break;
        default: src = X_t; Cin = 256; Dh = Bph;  Dl = Bpl;  roff = 1024; break;
    }
    if (Cin == 256 && bx >= 8) return;
#pragma unroll
    for (int j = 0; j < 32; j += 8)
        t[ty + j][tx] = src[(long)(by * 32 + ty + j) * Cin + bx * 32 + tx];
    __syncthreads();
#pragma unroll
    for (int j = 0; j < 32; j += 8) {
        __nv_bfloat16 h, l;
        bf_split(t[tx][ty + j], h, l);
        const long o = (long)(roff + bx * 32 + ty + j) * 1024 + by * 32 + tx;
        Dh[o] = h; Dl[o] = l;
    }
}

// ---------------- split x into bf16 hi/lo planes -----------------------------
__global__ void split_x(const float* __restrict__ x,
                        __nv_bfloat16* __restrict__ xh, __nv_bfloat16* __restrict__ xl)
{
    const long n4 = (long)MTOT * D_MODEL / 4;
    for (long i = (long)blockIdx.x * blockDim.x + threadIdx.x; i < n4;
         i += (long)gridDim.x * blockDim.x) {
        float4 v = ((const float4*)x)[i];
        __nv_bfloat16 h[4], l[4];
        bf_split(v.x, h[0], l[0]); bf_split(v.y, h[1], l[1]);
        bf_split(v.z, h[2], l[2]); bf_split(v.w, h[3], l[3]);
        uint2 H, L;
        H.x = pack2(h[0], h[1]); H.y = pack2(h[2], h[3]);
        L.x = pack2(l[0], l[1]); L.y = pack2(l[2], l[3]);
        ((uint2*)xh)[i] = H;
        ((uint2*)xl)[i] = L;
    }
}

// ---------------- causal cumulative scan (cols 512..1280 of H) --------------
__global__ void scan_partial(float* __restrict__ Hc, float* __restrict__ cs)
{
    const int col = blockIdx.x * 128 + threadIdx.x;   // 0..767
    const int ch  = blockIdx.y;
    const int b   = blockIdx.z;
    const long base = ((long)b * SEQ + (long)ch * TCH) * NPROJ + col;
    float run = 0.f;
    for (int t = 0; t < TCH; t++) {
        run += Hc[base + (long)t * NPROJ];
        Hc[base + (long)t * NPROJ] = run;
    }
    cs[((long)b * NCH + ch) * SCANC + col] = run;
}

__global__ void scan_offsets(float* __restrict__ cs)
{
    const int i = blockIdx.x * blockDim.x + threadIdx.x;
    if (i >= BATCH * SCANC) return;
    const int b = i / SCANC, col = i % SCANC;
    float off = 0.f;
    for (int ch = 0; ch < NCH; ch++) {
        const long idx = ((long)b * NCH + ch) * SCANC + col;
        const float v = cs[idx];
        cs[idx] = off;
        off += v;
    }
}

// ---------------- fused scan-apply + G build (bf16 split output) -------------
__global__ void apply_build(const float* __restrict__ H, const float* __restrict__ cs,
                            const float* __restrict__ alpha,
                            __nv_bfloat16* __restrict__ Gh, __nv_bfloat16* __restrict__ Gl)
{
    const int i = blockIdx.x * blockDim.x + threadIdx.x;
    if (i >= MTOT * RANK) return;
    const int m = i / RANK, r = i % RANK;
    const int t = m % SEQ, b = m / SEQ, ch = t / TCH;
    const float inv = 1.0f / (float)(t + 1);
    const float* hrow = H + (long)m * NPROJ;
    const float* co = cs + ((long)b * NCH + ch) * SCANC;
    const float cb = hrow[512 + r]  + co[r];
    const float ct = hrow[768 + r]  + co[256 + r];
    const float z  = (hrow[1024 + r] + co[512 + r]) * inv;
    const float gb = hrow[r] * cb * inv;
    const float gt = alpha[0] * hrow[256 + r] * z * ct * inv;
    const long o = (long)m * R2 + r;
    __nv_bfloat16 h, l;
    bf_split(gb, h, l); Gh[o] = h;        Gl[o] = l;
    bf_split(gt, h, l); Gh[o + RANK] = h; Gl[o + RANK] = l;
}

// bo[d] = sum_e Wo[d,e] * (bias_b[e] + alpha*bias_t[e])
__global__ void bo_kernel(const float* __restrict__ Wo, const float* __restrict__ bb,
                          const float* __restrict__ bt, const float* __restrict__ alpha,
                          float* __restrict__ bo)
{
    const int w = (blockIdx.x * blockDim.x + threadIdx.x) >> 5;
    const int lane = threadIdx.x & 31;
    if (w >= D_MODEL) return;
    const float a = alpha[0];
    float s = 0.f;
    for (int e = lane; e < D_MODEL; e += 32)
        s += Wo[(long)w * D_MODEL + e] * (bb[e] + a * bt[e]);
#pragma unroll
    for (int o = 16; o; o >>= 1) s += __shfl_xor_sync(0xFFFFFFFFu, s, o);
    if (lane == 0) bo[w] = s;
}

// ---------------- launch ------------------------------------------------------
extern "C" void kernel_launch(void* const* d_in, const int* in_sizes, int n_in,
                              void* d_out, int out_size)
{
    const float* x      = (const float*)d_in[0];
    const float* Wq     = (const float*)d_in[1];
    const float* Wk     = (const float*)d_in[2];
    const float* Wo     = (const float*)d_in[3];
    const float* U_b    = (const float*)d_in[4];
    const float* V_b    = (const float*)d_in[5];
    const float* W_b    = (const float*)d_in[6];
    const float* bias_b = (const float*)d_in[7];
    const float* U_t    = (const float*)d_in[8];
    const float* V_t    = (const float*)d_in[9];
    const float* W_t    = (const float*)d_in[10];
    const float* X_t    = (const float*)d_in[11];
    const float* bias_t = (const float*)d_in[12];
    const float* alpha  = (const float*)d_in[13];
    float* out = (float*)d_out;

    float *H, *bo, *cs;
    __nv_bfloat16 *xh, *xl, *Gh, *Gl, *Bph, *Bpl, *UWoh, *UWol;
    __nv_bfloat16 *WqTh, *WqTl, *WkTh, *WkTl, *VcTh, *VcTl, *WcTh, *WcTl, *UcTh, *UcTl, *Woh, *Wol;
    cudaGetSymbolAddress((void**)&H,    g_H);
    cudaGetSymbolAddress((void**)&xh,   g_xh);
    cudaGetSymbolAddress((void**)&xl,   g_xl);
    cudaGetSymbolAddress((void**)&Gh,   g_Gh);
    cudaGetSymbolAddress((void**)&Gl,   g_Gl);
    cudaGetSymbolAddress((void**)&Bph,  g_Bph);
    cudaGetSymbolAddress((void**)&Bpl,  g_Bpl);
    cudaGetSymbolAddress((void**)&UWoh, g_UWoh);
    cudaGetSymbolAddress((void**)&UWol, g_UWol);
    cudaGetSymbolAddress((void**)&WqTh, g_WqTh);
    cudaGetSymbolAddress((void**)&WqTl, g_WqTl);
    cudaGetSymbolAddress((void**)&WkTh, g_WkTh);
    cudaGetSymbolAddress((void**)&WkTl, g_WkTl);
    cudaGetSymbolAddress((void**)&VcTh, g_VcTh);
    cudaGetSymbolAddress((void**)&VcTl, g_VcTl);
    cudaGetSymbolAddress((void**)&WcTh, g_WcTh);
    cudaGetSymbolAddress((void**)&WcTl, g_WcTl);
    cudaGetSymbolAddress((void**)&UcTh, g_UcTh);
    cudaGetSymbolAddress((void**)&UcTl, g_UcTl);
    cudaGetSymbolAddress((void**)&Woh,  g_Woh);
    cudaGetSymbolAddress((void**)&Wol,  g_Wol);
    cudaGetSymbolAddress((void**)&bo,   g_bo);
    cudaGetSymbolAddress((void**)&cs,   g_cs);

    cudaFuncSetAttribute(gemm_prep,        cudaFuncAttributeMaxDynamicSharedMemorySize, PRE_SMEM);
    cudaFuncSetAttribute(gemm_main<false>, cudaFuncAttributeMaxDynamicSharedMemorySize, PRE_SMEM);
    cudaFuncSetAttribute(gemm_main<true>,  cudaFuncAttributeMaxDynamicSharedMemorySize, PRE_SMEM);

    // ---- prep: transposes/concats + bias fold + x split ----
    dim3 tgrid(32, 32, 10), tblk(32, 8);
    trans_batched<<<tgrid, tblk>>>(Wq, Wk, V_b, V_t, W_b, W_t, U_b, U_t, X_t, Wo,
                                   WqTh, WqTl, WkTh, WkTl, VcTh, VcTl, WcTh, WcTl,
                                   UcTh, UcTl, Bph, Bpl, Woh, Wol);
    bo_kernel<<<128, 256>>>(Wo, bias_b, bias_t, alpha, bo);
    split_x<<<4096, 256>>>(x, xh, xl);

    // ---- prep GEMMs: 96 tiles x 3 k-slices = 288 CTAs (one full wave) ----
    dim3 gprep(96, 3);
    gemm_prep<<<gprep, 256, PRE_SMEM>>>(VcTh, VcTl, WqTh, WqTl, WcTh, WcTl, WkTh, WkTl,
                                        Woh, Wol, UcTh, UcTl, H);
    combine_prep<<<1024, 256>>>(H, Bph, Bpl, UWoh, UWol);

    // ---- main: H = x @ Bp^T  [8192, 1280] ----
    dim3 gH(NPROJ / 128, MTOT / 128);
    gemm_main<false><<<gH, 128, PRE_SMEM>>>(xh, xl, Bph, Bpl, H, NPROJ, D_MODEL, nullptr);

    // ---- causal scan over H cols [512,1280) ----
    dim3 gs(SCANC / 128, NCH, BATCH);
    scan_partial<<<gs, 128>>>(H + 512, cs);
    scan_offsets<<<(BATCH * SCANC + 255) / 256, 256>>>(cs);

    // ---- fused apply + build G (bf16 split) ----
    apply_build<<<(MTOT * RANK + 255) / 256, 256>>>(H, cs, alpha, Gh, Gl);

    // ---- out = G @ UWo^T + bo  [8192, 1024] ----
    dim3 gO(D_MODEL / 128, MTOT / 128);
    gemm_main<true><<<gO, 128, PRE_SMEM>>>(Gh, Gl, UWoh, UWol, out, D_MODEL, R2, bo);
}

// round 12
// speedup vs baseline: 2.6589x; 1.0271x over previous
#include <cuda_runtime.h>
#include <cuda_bf16.h>
#include <cstdint>

// Problem constants (fixed shapes)
#define D_MODEL 1024
#define RANK    256
#define R2      (2*RANK)          // 512
#define NPROJ   (R2 + R2 + RANK)  // 1280 = [a_b|a_t | c_b|c_t | z]
#define BATCH   4
#define SEQ     2048
#define MTOT    (BATCH*SEQ)       // 8192
#define TCH     128
#define NCH     (SEQ/TCH)         // 16
#define SCANC   (R2 + RANK)       // 768 scanned columns
#define PSLICE  (1024*1024 + 1024*512)   // 1.5M floats per k-slice partial

// ---------------- scratch (device globals; no cudaMalloc allowed) ------------
__device__ float         g_H   [MTOT*NPROJ];   // reused as prep partial scratch first
__device__ __nv_bfloat16 g_xh  [MTOT*D_MODEL];
__device__ __nv_bfloat16 g_xl  [MTOT*D_MODEL];
__device__ __nv_bfloat16 g_Gh  [MTOT*R2];
__device__ __nv_bfloat16 g_Gl  [MTOT*R2];
__device__ __nv_bfloat16 g_Bph [NPROJ*D_MODEL];
__device__ __nv_bfloat16 g_Bpl [NPROJ*D_MODEL];
__device__ __nv_bfloat16 g_UWoh[D_MODEL*R2];
__device__ __nv_bfloat16 g_UWol[D_MODEL*R2];
__device__ __nv_bfloat16 g_WqTh[D_MODEL*D_MODEL], g_WqTl[D_MODEL*D_MODEL];
__device__ __nv_bfloat16 g_WkTh[D_MODEL*D_MODEL], g_WkTl[D_MODEL*D_MODEL];
__device__ __nv_bfloat16 g_VcTh[R2*D_MODEL],      g_VcTl[R2*D_MODEL];
__device__ __nv_bfloat16 g_WcTh[R2*D_MODEL],      g_WcTl[R2*D_MODEL];
__device__ __nv_bfloat16 g_UcTh[R2*D_MODEL],      g_UcTl[R2*D_MODEL];
__device__ __nv_bfloat16 g_Woh [D_MODEL*D_MODEL], g_Wol [D_MODEL*D_MODEL];
__device__ float g_bo [D_MODEL];
__device__ float g_cs [BATCH*NCH*SCANC];

// ====================== helpers ==============================================
#define LDSM_X4(R, A) \
    asm volatile("ldmatrix.sync.aligned.m8n8.x4.shared.b16 {%0,%1,%2,%3}, [%4];" \
        : "=r"((R)[0]), "=r"((R)[1]), "=r"((R)[2]), "=r"((R)[3]) : "r"(A))
#define MMA_BF16(D, Ar, Br) \
    asm volatile("mma.sync.aligned.m16n8k16.row.col.f32.bf16.bf16.f32 " \
        "{%0,%1,%2,%3}, {%4,%5,%6,%7}, {%8,%9}, {%0,%1,%2,%3};" \
        : "+f"((D)[0]), "+f"((D)[1]), "+f"((D)[2]), "+f"((D)[3]) \
        : "r"((Ar)[0]), "r"((Ar)[1]), "r"((Ar)[2]), "r"((Ar)[3]), \
          "r"((Br)[0]), "r"((Br)[1]))

__device__ __forceinline__ uint32_t smem_u32(const void* p) {
    uint32_t a;
    asm("{ .reg .u64 t; cvta.to.shared.u64 t, %1; cvt.u32.u64 %0, t; }" : "=r"(a) : "l"(p));
    return a;
}

// paired-row swizzled byte offset (64B logical rows in 128B physical rows)
__device__ __forceinline__ uint32_t swoff(int m, int c) {
    const int p  = m >> 1;
    const int cc = (((m & 1) << 2) | c) ^ (p & 7);
    return (uint32_t)(p * 128 + cc * 16);
}

__device__ __forceinline__ uint32_t pack2(__nv_bfloat16 x, __nv_bfloat16 y) {
    return (uint32_t)__bfloat16_as_ushort(x) | ((uint32_t)__bfloat16_as_ushort(y) << 16);
}

__device__ __forceinline__ void bf_split(float v, __nv_bfloat16& h, __nv_bfloat16& l) {
    h = __float2bfloat16(v);
    l = __float2bfloat16(v - __bfloat162float(h));
}

__device__ __forceinline__ void cpasync16(uint32_t dst, const void* src) {
    asm volatile("cp.async.cg.shared.global [%0], [%1], 16;" :: "r"(dst), "l"(src));
}
#define CP_COMMIT() asm volatile("cp.async.commit_group;" ::: "memory")
#define CP_WAIT1()  asm volatile("cp.async.wait_group 1;"  ::: "memory")

// ====================== shared 4-warp GEMM core ===============================
// 128x128 CTA tile, 4 warps (64x64 warp tiles), BK=32, 3-stage cp.async, 96 KB.
// acc[4][8][4] += (Ah+Al)[M,K] @ (Bh+Bl)[N,K]^T over k-iters [kbeg,kend).
#define TILE_B     8192
#define STAGE_B    32768
#define PRE_SMEM   (3*STAGE_B)   // 96 KB

__device__ __forceinline__ void gemm_core4(
    const __nv_bfloat16* __restrict__ Ah_g, const __nv_bfloat16* __restrict__ Al_g,
    const __nv_bfloat16* __restrict__ Bh_g, const __nv_bfloat16* __restrict__ Bl_g,
    int K, int kbeg, int kend, long bm, long bn, uint32_t sb, float acc[4][8][4])
{
    const int tid = threadIdx.x, wid = tid >> 5, lane = tid & 31;
    const int warpM = wid & 1, warpN = wid >> 1;      // 2 x 2, 64x64 tiles

    uint32_t offA0[2], offB0[2];
#pragma unroll
    for (int kg = 0; kg < 2; kg++) {
        offA0[kg] = swoff(warpM * 64 + (lane & 15), 2 * kg + (lane >> 4));
        offB0[kg] = swoff(warpN * 64 + ((lane >> 4) << 3) + (lane & 7),
                          2 * kg + ((lane >> 3) & 1));
    }

    // cp.async: 2048 chunks/stage, 128 threads -> 16 per thread
    const int mrow = tid >> 2, mc = tid & 3;   // rows 0..31, chunks 0..3
    uint32_t soA[4];
#pragma unroll
    for (int rep = 0; rep < 4; rep++) soA[rep] = swoff(mrow + 32 * rep, mc);

    auto issue = [&](int kt) {
        const uint32_t base = sb + (uint32_t)(kt % 3) * STAGE_B;
        const long koff = (long)kt * 32 + mc * 8;
#pragma unroll
        for (int rep = 0; rep < 4; rep++) {
            const long gA = (bm + mrow + 32 * rep) * (long)K + koff;
            const long gB = (bn + mrow + 32 * rep) * (long)K + koff;
            cpasync16(base + soA[rep],            Ah_g + gA);
            cpasync16(base + TILE_B + soA[rep],   Al_g + gA);
            cpasync16(base + 2*TILE_B + soA[rep], Bh_g + gB);
            cpasync16(base + 3*TILE_B + soA[rep], Bl_g + gB);
        }
    };

    issue(kbeg);     CP_COMMIT();
    issue(kbeg + 1); CP_COMMIT();

#pragma unroll 1
    for (int kt = kbeg; kt < kend; kt++) {
        CP_WAIT1();
        __syncthreads();
        if (kt + 2 < kend) issue(kt + 2);
        CP_COMMIT();

        const uint32_t bb = sb + (uint32_t)(kt % 3) * STAGE_B;
#pragma unroll
        for (int kg = 0; kg < 2; kg++) {
            uint32_t bh[8][2], bl[8][2];
#pragma unroll
            for (int jp = 0; jp < 4; jp++) {
                uint32_t rh[4], rl[4];
                const uint32_t bo_ = offB0[kg] + (uint32_t)jp * 1024;
                LDSM_X4(rh, bb + 2*TILE_B + bo_);
                LDSM_X4(rl, bb + 3*TILE_B + bo_);
                bh[2*jp][0]   = rh[0]; bh[2*jp][1]   = rh[1];
                bh[2*jp+1][0] = rh[2]; bh[2*jp+1][1] = rh[3];
                bl[2*jp][0]   = rl[0]; bl[2*jp][1]   = rl[1];
                bl[2*jp+1][0] = rl[2]; bl[2*jp+1][1] = rl[3];
            }
#pragma unroll
            for (int i = 0; i < 4; i++) {
                uint32_t ah[4], al[4];
                const uint32_t ao = bb + offA0[kg] + (uint32_t)i * 1024;
                LDSM_X4(ah, ao);
                LDSM_X4(al, ao + TILE_B);
#pragma unroll
                for (int j = 0; j < 8; j++) {
                    MMA_BF16(acc[i][j], ah, bh[j]);
                    MMA_BF16(acc[i][j], ah, bl[j]);
                    MMA_BF16(acc[i][j], al, bh[j]);
                }
            }
        }
    }
}

// ---------------- main GEMM (fp32 output, optional bias) ---------------------
template<bool BIAS>
__global__ __launch_bounds__(128, 2)
void gemm_main(const __nv_bfloat16* __restrict__ Ah_g, const __nv_bfloat16* __restrict__ Al_g,
               const __nv_bfloat16* __restrict__ Bh_g, const __nv_bfloat16* __restrict__ Bl_g,
               float* __restrict__ C, int N, int K, const float* __restrict__ bias)
{
    extern __shared__ __align__(128) char sm[];
    const uint32_t sb = smem_u32(sm);
    const long bm = (long)blockIdx.y * 128, bn = (long)blockIdx.x * 128;

    float acc[4][8][4];
#pragma unroll
    for (int i = 0; i < 4; i++)
#pragma unroll
        for (int j = 0; j < 8; j++)
#pragma unroll
            for (int q = 0; q < 4; q++) acc[i][j][q] = 0.f;

    gemm_core4(Ah_g, Al_g, Bh_g, Bl_g, K, 0, K / 32, bm, bn, sb, acc);

    const int tid = threadIdx.x, wid = tid >> 5, lane = tid & 31;
    const int warpM = wid & 1, warpN = wid >> 1;
    const int g = lane >> 2, tg = lane & 3;
#pragma unroll
    for (int i = 0; i < 4; i++) {
        const long row = bm + warpM * 64 + i * 16 + g;
#pragma unroll
        for (int j = 0; j < 8; j++) {
            const int col = (int)bn + warpN * 64 + j * 8 + 2 * tg;
            float b0 = 0.f, b1 = 0.f;
            if (BIAS) { b0 = bias[col]; b1 = bias[col + 1]; }
            float2 v0 = make_float2(acc[i][j][0] + b0, acc[i][j][1] + b1);
            float2 v1 = make_float2(acc[i][j][2] + b0, acc[i][j][3] + b1);
            *(float2*)(C + row * N + col)       = v0;
            *(float2*)(C + (row + 8) * N + col) = v1;
        }
    }
}

// ---------------- prep GEMM: compact tiles, split-K x3, 4-warp core ----------
// tiles 0..31 : op0 Bp[0,512)   = VcT @ WqT^T  (4 m-tiles x 8 n-tiles)
// tiles 32..63: op1 Bp[512,1024)= WcT @ WkT^T
// tiles 64..95: op2 UWo[1024,512]= Wo @ UcT^T  (8 m-tiles x 4 n-tiles)
// blockIdx.y = k-slice s in {0,1,2}: iters [11s, min(11s+11,32))
__global__ __launch_bounds__(128, 2)
void gemm_prep(const __nv_bfloat16* __restrict__ VcTh, const __nv_bfloat16* __restrict__ VcTl,
               const __nv_bfloat16* __restrict__ WqTh, const __nv_bfloat16* __restrict__ WqTl,
               const __nv_bfloat16* __restrict__ WcTh, const __nv_bfloat16* __restrict__ WcTl,
               const __nv_bfloat16* __restrict__ WkTh, const __nv_bfloat16* __restrict__ WkTl,
               const __nv_bfloat16* __restrict__ Woh,  const __nv_bfloat16* __restrict__ Wol,
               const __nv_bfloat16* __restrict__ UcTh, const __nv_bfloat16* __restrict__ UcTl,
               float* __restrict__ P)
{
    const int t = blockIdx.x, s = blockIdx.y;
    const __nv_bfloat16 *Ah, *Al, *Bh, *Bl;
    long bm, bn, ooff; int ldc;
    if (t < 32)      { Ah=VcTh; Al=VcTl; Bh=WqTh; Bl=WqTl; bm=(t>>3)*128;      bn=(t&7)*128;      ldc=1024; ooff=0; }
    else if (t < 64) { Ah=WcTh; Al=WcTl; Bh=WkTh; Bl=WkTl; bm=((t-32)>>3)*128; bn=((t-32)&7)*128; ldc=1024; ooff=512L*1024; }
    else             { Ah=Woh;  Al=Wol;  Bh=UcTh; Bl=UcTl; bm=((t-64)>>2)*128; bn=((t-64)&3)*128; ldc=512;  ooff=1024L*1024; }
    const int K = 1024;
    const int kbeg = s * 11, kend = (s == 2) ? 32 : kbeg + 11;
    float* Cp = P + (long)s * PSLICE + ooff;

    extern __shared__ __align__(128) char sm[];
    const uint32_t sb = smem_u32(sm);

    float acc[4][8][4];
#pragma unroll
    for (int i = 0; i < 4; i++)
#pragma unroll
        for (int j = 0; j < 8; j++)
#pragma unroll
            for (int q = 0; q < 4; q++) acc[i][j][q] = 0.f;

    gemm_core4(Ah, Al, Bh, Bl, K, kbeg, kend, bm, bn, sb, acc);

    const int tid = threadIdx.x, wid = tid >> 5, lane = tid & 31;
    const int warpM = wid & 1, warpN = wid >> 1;
    const int g = lane >> 2, tg = lane & 3;
#pragma unroll
    for (int i = 0; i < 4; i++) {
        const long row = bm + warpM * 64 + i * 16 + g;
#pragma unroll
        for (int j = 0; j < 8; j++) {
            const int col = (int)bn + warpN * 64 + j * 8 + 2 * tg;
            *(float2*)(Cp + row * ldc + col)       = make_float2(acc[i][j][0], acc[i][j][1]);
            *(float2*)(Cp + (row + 8) * ldc + col) = make_float2(acc[i][j][2], acc[i][j][3]);
        }
    }
}

// combine 3 k-slice partials -> bf16 hi/lo planes
__global__ void combine_prep(const float* __restrict__ P,
                             __nv_bfloat16* __restrict__ Bph, __nv_bfloat16* __restrict__ Bpl,
                             __nv_bfloat16* __restrict__ UWoh, __nv_bfloat16* __restrict__ UWol)
{
    const long n = PSLICE;
    for (long i = (long)blockIdx.x * blockDim.x + threadIdx.x; i < n;
         i += (long)gridDim.x * blockDim.x) {
        const float v = P[i] + P[PSLICE + i] + P[2L*PSLICE + i];
        __nv_bfloat16 h, l;
        bf_split(v, h, l);
        if (i < 1024L * 1024) { Bph[i] = h; Bpl[i] = l; }
        else { UWoh[i - 1024L*1024] = h; UWol[i - 1024L*1024] = l; }
    }
}

// ====================== batched transpose / concat / split ===================
__global__ void trans_batched(const float* __restrict__ Wq, const float* __restrict__ Wk,
                              const float* __restrict__ V_b, const float* __restrict__ V_t,
                              const float* __restrict__ W_b, const float* __restrict__ W_t,
                              const float* __restrict__ U_b, const float* __restrict__ U_t,
                              const float* __restrict__ X_t, const float* __restrict__ Wo,
                              __nv_bfloat16* __restrict__ WqTh, __nv_bfloat16* __restrict__ WqTl,
                              __nv_bfloat16* __restrict__ WkTh, __nv_bfloat16* __restrict__ WkTl,
                              __nv_bfloat16* __restrict__ VcTh, __nv_bfloat16* __restrict__ VcTl,
                              __nv_bfloat16* __restrict__ WcTh, __nv_bfloat16* __restrict__ WcTl,
                              __nv_bfloat16* __restrict__ UcTh, __nv_bfloat16* __restrict__ UcTl,
                              __nv_bfloat16* __restrict__ Bph,  __nv_bfloat16* __restrict__ Bpl,
                              __nv_bfloat16* __restrict__ Woh,  __nv_bfloat16* __restrict__ Wol)
{
    __shared__ float t[32][33];
    const int z = blockIdx.z;
    const int bx = blockIdx.x, by = blockIdx.y;
    const int tx = threadIdx.x, ty = threadIdx.y;

    if (z == 9) {
#pragma unroll
        for (int j = 0; j < 32; j += 8) {
            const long o = (long)(by * 32 + ty + j) * 1024 + bx * 32 + tx;
            __nv_bfloat16 h, l;
            bf_split(Wo[o], h, l);
            Woh[o] = h; Wol[o] = l;
        }
        return;
    }

    const float* src; int Cin;
    __nv_bfloat16 *Dh, *Dl; int roff = 0;
    switch (z) {
        case 0: src = Wq;  Cin = 1024; Dh = WqTh; Dl = WqTl; break;
        case 1: src = Wk;  Cin = 1024; Dh = WkTh; Dl = WkTl; break;
        case 2: src = V_b; Cin = 256;  Dh = VcTh; Dl = VcTl; roff = 0;    break;
        case 3: src = V_t; Cin = 256;  Dh = VcTh; Dl = VcTl; roff = 256;  break;
        case 4: src = W_b; Cin = 256;  Dh = WcTh; Dl = WcTl; roff = 0;    break;
        case 5: src = W_t; Cin = 256;  Dh = WcTh; Dl = WcTl; roff = 256;  break;
        case 6: src = U_b; Cin = 256;  Dh = UcTh; Dl = UcTl; roff = 0;    break;
        case 7: src = U_t; Cin = 256;  Dh = UcTh; Dl = UcTl; roff = 256;  break;
        default: src = X_t; Cin = 256; Dh = Bph;  Dl = Bpl;  roff = 1024; break;
    }
    if (Cin == 256 && bx >= 8) return;
#pragma unroll
    for (int j = 0; j < 32; j += 8)
        t[ty + j][tx] = src[(long)(by * 32 + ty + j) * Cin + bx * 32 + tx];
    __syncthreads();
#pragma unroll
    for (int j = 0; j < 32; j += 8) {
        __nv_bfloat16 h, l;
        bf_split(t[tx][ty + j], h, l);
        const long o = (long)(roff + bx * 32 + ty + j) * 1024 + by * 32 + tx;
        Dh[o] = h; Dl[o] = l;
    }
}

// ---------------- split x into bf16 hi/lo planes -----------------------------
__global__ void split_x(const float* __restrict__ x,
                        __nv_bfloat16* __restrict__ xh, __nv_bfloat16* __restrict__ xl)
{
    const long n4 = (long)MTOT * D_MODEL / 4;
    for (long i = (long)blockIdx.x * blockDim.x + threadIdx.x; i < n4;
         i += (long)gridDim.x * blockDim.x) {
        float4 v = ((const float4*)x)[i];
        __nv_bfloat16 h[4], l[4];
        bf_split(v.x, h[0], l[0]); bf_split(v.y, h[1], l[1]);
        bf_split(v.z, h[2], l[2]); bf_split(v.w, h[3], l[3]);
        uint2 H, L;
        H.x = pack2(h[0], h[1]); H.y = pack2(h[2], h[3]);
        L.x = pack2(l[0], l[1]); L.y = pack2(l[2], l[3]);
        ((uint2*)xh)[i] = H;
        ((uint2*)xl)[i] = L;
    }
}

// ---------------- causal cumulative scan (cols 512..1280 of H) --------------
__global__ void scan_partial(float* __restrict__ Hc, float* __restrict__ cs)
{
    const int col = blockIdx.x * 128 + threadIdx.x;   // 0..767
    const int ch  = blockIdx.y;
    const int b   = blockIdx.z;
    const long base = ((long)b * SEQ + (long)ch * TCH) * NPROJ + col;
    float run = 0.f;
    for (int t = 0; t < TCH; t++) {
        run += Hc[base + (long)t * NPROJ];
        Hc[base + (long)t * NPROJ] = run;
    }
    cs[((long)b * NCH + ch) * SCANC + col] = run;
}

__global__ void scan_offsets(float* __restrict__ cs)
{
    const int i = blockIdx.x * blockDim.x + threadIdx.x;
    if (i >= BATCH * SCANC) return;
    const int b = i / SCANC, col = i % SCANC;
    float off = 0.f;
    for (int ch = 0; ch < NCH; ch++) {
        const long idx = ((long)b * NCH + ch) * SCANC + col;
        const float v = cs[idx];
        cs[idx] = off;
        off += v;
    }
}

// ---------------- fused scan-apply + G build (bf16 split output) -------------
__global__ void apply_build(const float* __restrict__ H, const float* __restrict__ cs,
                            const float* __restrict__ alpha,
                            __nv_bfloat16* __restrict__ Gh, __nv_bfloat16* __restrict__ Gl)
{
    const int i = blockIdx.x * blockDim.x + threadIdx.x;
    if (i >= MTOT * RANK) return;
    const int m = i / RANK, r = i % RANK;
    const int t = m % SEQ, b = m / SEQ, ch = t / TCH;
    const float inv = 1.0f / (float)(t + 1);
    const float* hrow = H + (long)m * NPROJ;
    const float* co = cs + ((long)b * NCH + ch) * SCANC;
    const float cb = hrow[512 + r]  + co[r];
    const float ct = hrow[768 + r]  + co[256 + r];
    const float z  = (hrow[1024 + r] + co[512 + r]) * inv;
    const float gb = hrow[r] * cb * inv;
    const float gt = alpha[0] * hrow[256 + r] * z * ct * inv;
    const long o = (long)m * R2 + r;
    __nv_bfloat16 h, l;
    bf_split(gb, h, l); Gh[o] = h;        Gl[o] = l;
    bf_split(gt, h, l); Gh[o + RANK] = h; Gl[o + RANK] = l;
}

// bo[d] = sum_e Wo[d,e] * (bias_b[e] + alpha*bias_t[e])
__global__ void bo_kernel(const float* __restrict__ Wo, const float* __restrict__ bb,
                          const float* __restrict__ bt, const float* __restrict__ alpha,
                          float* __restrict__ bo)
{
    const int w = (blockIdx.x * blockDim.x + threadIdx.x) >> 5;
    const int lane = threadIdx.x & 31;
    if (w >= D_MODEL) return;
    const float a = alpha[0];
    float s = 0.f;
    for (int e = lane; e < D_MODEL; e += 32)
        s += Wo[(long)w * D_MODEL + e] * (bb[e] + a * bt[e]);
#pragma unroll
    for (int o = 16; o; o >>= 1) s += __shfl_xor_sync(0xFFFFFFFFu, s, o);
    if (lane == 0) bo[w] = s;
}

// ---------------- launch ------------------------------------------------------
extern "C" void kernel_launch(void* const* d_in, const int* in_sizes, int n_in,
                              void* d_out, int out_size)
{
    const float* x      = (const float*)d_in[0];
    const float* Wq     = (const float*)d_in[1];
    const float* Wk     = (const float*)d_in[2];
    const float* Wo     = (const float*)d_in[3];
    const float* U_b    = (const float*)d_in[4];
    const float* V_b    = (const float*)d_in[5];
    const float* W_b    = (const float*)d_in[6];
    const float* bias_b = (const float*)d_in[7];
    const float* U_t    = (const float*)d_in[8];
    const float* V_t    = (const float*)d_in[9];
    const float* W_t    = (const float*)d_in[10];
    const float* X_t    = (const float*)d_in[11];
    const float* bias_t = (const float*)d_in[12];
    const float* alpha  = (const float*)d_in[13];
    float* out = (float*)d_out;

    float *H, *bo, *cs;
    __nv_bfloat16 *xh, *xl, *Gh, *Gl, *Bph, *Bpl, *UWoh, *UWol;
    __nv_bfloat16 *WqTh, *WqTl, *WkTh, *WkTl, *VcTh, *VcTl, *WcTh, *WcTl, *UcTh, *UcTl, *Woh, *Wol;
    cudaGetSymbolAddress((void**)&H,    g_H);
    cudaGetSymbolAddress((void**)&xh,   g_xh);
    cudaGetSymbolAddress((void**)&xl,   g_xl);
    cudaGetSymbolAddress((void**)&Gh,   g_Gh);
    cudaGetSymbolAddress((void**)&Gl,   g_Gl);
    cudaGetSymbolAddress((void**)&Bph,  g_Bph);
    cudaGetSymbolAddress((void**)&Bpl,  g_Bpl);
    cudaGetSymbolAddress((void**)&UWoh, g_UWoh);
    cudaGetSymbolAddress((void**)&UWol, g_UWol);
    cudaGetSymbolAddress((void**)&WqTh, g_WqTh);
    cudaGetSymbolAddress((void**)&WqTl, g_WqTl);
    cudaGetSymbolAddress((void**)&WkTh, g_WkTh);
    cudaGetSymbolAddress((void**)&WkTl, g_WkTl);
    cudaGetSymbolAddress((void**)&VcTh, g_VcTh);
    cudaGetSymbolAddress((void**)&VcTl, g_VcTl);
    cudaGetSymbolAddress((void**)&WcTh, g_WcTh);
    cudaGetSymbolAddress((void**)&WcTl, g_WcTl);
    cudaGetSymbolAddress((void**)&UcTh, g_UcTh);
    cudaGetSymbolAddress((void**)&UcTl, g_UcTl);
    cudaGetSymbolAddress((void**)&Woh,  g_Woh);
    cudaGetSymbolAddress((void**)&Wol,  g_Wol);
    cudaGetSymbolAddress((void**)&bo,   g_bo);
    cudaGetSymbolAddress((void**)&cs,   g_cs);

    cudaFuncSetAttribute(gemm_prep,        cudaFuncAttributeMaxDynamicSharedMemorySize, PRE_SMEM);
    cudaFuncSetAttribute(gemm_main<false>, cudaFuncAttributeMaxDynamicSharedMemorySize, PRE_SMEM);
    cudaFuncSetAttribute(gemm_main<true>,  cudaFuncAttributeMaxDynamicSharedMemorySize, PRE_SMEM);

    // ---- prep: transposes/concats + bias fold + x split ----
    dim3 tgrid(32, 32, 10), tblk(32, 8);
    trans_batched<<<tgrid, tblk>>>(Wq, Wk, V_b, V_t, W_b, W_t, U_b, U_t, X_t, Wo,
                                   WqTh, WqTl, WkTh, WkTl, VcTh, VcTl, WcTh, WcTl,
                                   UcTh, UcTl, Bph, Bpl, Woh, Wol);
    bo_kernel<<<128, 256>>>(Wo, bias_b, bias_t, alpha, bo);
    split_x<<<4096, 256>>>(x, xh, xl);

    // ---- prep GEMMs: 96 tiles x 3 k-slices = 288 CTAs (one dual-CTA wave) ----
    dim3 gprep(96, 3);
    gemm_prep<<<gprep, 128, PRE_SMEM>>>(VcTh, VcTl, WqTh, WqTl, WcTh, WcTl, WkTh, WkTl,
                                        Woh, Wol, UcTh, UcTl, H);
    combine_prep<<<1024, 256>>>(H, Bph, Bpl, UWoh, UWol);

    // ---- main: H = x @ Bp^T  [8192, 1280] ----
    dim3 gH(NPROJ / 128, MTOT / 128);
    gemm_main<false><<<gH, 128, PRE_SMEM>>>(xh, xl, Bph, Bpl, H, NPROJ, D_MODEL, nullptr);

    // ---- causal scan over H cols [512,1280) ----
    dim3 gs(SCANC / 128, NCH, BATCH);
    scan_partial<<<gs, 128>>>(H + 512, cs);
    scan_offsets<<<(BATCH * SCANC + 255) / 256, 256>>>(cs);

    // ---- fused apply + build G (bf16 split) ----
    apply_build<<<(MTOT * RANK + 255) / 256, 256>>>(H, cs, alpha, Gh, Gl);

    // ---- out = G @ UWo^T + bo  [8192, 1024] ----
    dim3 gO(D_MODEL / 128, MTOT / 128);
    gemm_main<true><<<gO, 128, PRE_SMEM>>>(Gh, Gl, UWoh, UWol, out, D_MODEL, R2, bo);
}